// round 5
// baseline (speedup 1.0000x reference)
#include <cuda_runtime.h>
#include <cuda_bf16.h>
#include <mma.h>
#include <math.h>

using namespace nvcuda;

// Problem constants
constexpr int B_   = 2;
constexpr int L_   = 2048;
constexpr int HID_ = 2048;
constexpr int H_   = 16;
constexpr int D_   = 128;
constexpr int M_   = B_ * L_;      // 4096 token rows
constexpr int BHL_ = B_ * H_ * L_;

// ---------------------------------------------------------------------------
// Static scratch (no cudaMalloc allowed)
// ---------------------------------------------------------------------------
__device__ __align__(16) __nv_bfloat16 g_xh[M_ * HID_];
__device__ __align__(16) __nv_bfloat16 g_xl[M_ * HID_];
__device__ __align__(16) __nv_bfloat16 g_wh[4][(size_t)HID_ * HID_];
__device__ __align__(16) __nv_bfloat16 g_wl[4][(size_t)HID_ * HID_];
__device__ __align__(16) float g_q[M_ * HID_];
__device__ __align__(16) float g_k[M_ * HID_];
__device__ __align__(16) float g_v[M_ * HID_];
__device__ __align__(16) float g_pq[M_ * HID_];   // phi(rope(q)) in [b][h][t][d]
__device__ __align__(16) float g_pk[M_ * HID_];   // phi(rope(k)) in [b][h][t][d]
__device__ __align__(16) float g_vt[M_ * HID_];   // v relayout     [b][h][t][d]
__device__ __align__(16) float g_beta[BHL_];      // [b][h][t]
__device__ __align__(16) float g_den[BHL_];       // [b][h][t]
__device__ __align__(16) float g_y[M_ * HID_];    // scan output [b][t][hid]
__device__ __align__(16) __nv_bfloat16 g_yh[M_ * HID_];
__device__ __align__(16) __nv_bfloat16 g_yl[M_ * HID_];
__device__ __align__(16) float g_cos[L_ * 64];
__device__ __align__(16) float g_sin[L_ * 64];

// ---------------------------------------------------------------------------
// fp32 -> (hi, lo) bf16 split
// ---------------------------------------------------------------------------
__global__ void split_kernel(const float* __restrict__ x,
                             __nv_bfloat16* __restrict__ hi,
                             __nv_bfloat16* __restrict__ lo, int n)
{
    int i = blockIdx.x * blockDim.x + threadIdx.x;
    if (i < n) {
        float v = x[i];
        __nv_bfloat16 h = __float2bfloat16(v);
        hi[i] = h;
        lo[i] = __float2bfloat16(v - __bfloat162float(h));
    }
}

// ---------------------------------------------------------------------------
// RoPE table (fp32 recipe matching the reference: cos(t * fl(inv_freq)))
// ---------------------------------------------------------------------------
__global__ void rope_table_kernel()
{
    int t = blockIdx.x;
    int i = threadIdx.x;           // 0..63
    double inv = pow(10000.0, -(double)i / 64.0);
    float invf = (float)inv;
    float f = (float)t * invf;
    g_cos[t * 64 + i] = cosf(f);
    g_sin[t * 64 + i] = sinf(f);
}

// ---------------------------------------------------------------------------
// Split-bf16 GEMM: C = A @ B (fp32-equivalent via hi*hi + hi*lo + lo*hi)
// A [M,K] row-major, B [K,N] row-major, C [M,N] fp32.
// 128x128 block tile, BK=32, 8 warps (4x2), warp tile 32x64 (2x4 wmma frags).
// ---------------------------------------------------------------------------
__global__ void __launch_bounds__(256)
gemm_split_kernel(const __nv_bfloat16* __restrict__ Ah,
                  const __nv_bfloat16* __restrict__ Al,
                  const __nv_bfloat16* __restrict__ Bh,
                  const __nv_bfloat16* __restrict__ Bl,
                  float* __restrict__ C, int Mdim, int Ndim, int Kdim)
{
    constexpr int BM = 128, BN = 128, BK = 32;
    constexpr int LDA = BK + 8;   // 40  (80B row stride, 16B-aligned)
    constexpr int LDB = BN + 8;   // 136 (272B row stride, 16B-aligned)

    __shared__ __nv_bfloat16 As[2][BM][LDA];
    __shared__ __nv_bfloat16 Bs[2][BK][LDB];

    const int tid = threadIdx.x;
    const int wid = tid >> 5;
    const int wr  = wid >> 1;   // 0..3
    const int wc  = wid & 1;    // 0..1
    const int m0  = blockIdx.y * BM;
    const int n0  = blockIdx.x * BN;

    wmma::fragment<wmma::accumulator, 16, 16, 16, float> acc[2][4];
#pragma unroll
    for (int i = 0; i < 2; i++)
#pragma unroll
        for (int j = 0; j < 4; j++) wmma::fill_fragment(acc[i][j], 0.0f);

    const int arow = tid >> 1, ahalf = tid & 1;   // 128 rows x 2 16-col segs
    const int brow = tid >> 3, bseg  = tid & 7;   // 32 rows x 8 16-col segs

    for (int k0 = 0; k0 < Kdim; k0 += BK) {
        {
            const uint4* sh = reinterpret_cast<const uint4*>(Ah + (size_t)(m0 + arow) * Kdim + k0 + ahalf * 16);
            const uint4* sl = reinterpret_cast<const uint4*>(Al + (size_t)(m0 + arow) * Kdim + k0 + ahalf * 16);
            uint4* dh = reinterpret_cast<uint4*>(&As[0][arow][ahalf * 16]);
            uint4* dl = reinterpret_cast<uint4*>(&As[1][arow][ahalf * 16]);
            dh[0] = sh[0]; dh[1] = sh[1];
            dl[0] = sl[0]; dl[1] = sl[1];
        }
        {
            const uint4* sh = reinterpret_cast<const uint4*>(Bh + (size_t)(k0 + brow) * Ndim + n0 + bseg * 16);
            const uint4* sl = reinterpret_cast<const uint4*>(Bl + (size_t)(k0 + brow) * Ndim + n0 + bseg * 16);
            uint4* dh = reinterpret_cast<uint4*>(&Bs[0][brow][bseg * 16]);
            uint4* dl = reinterpret_cast<uint4*>(&Bs[1][brow][bseg * 16]);
            dh[0] = sh[0]; dh[1] = sh[1];
            dl[0] = sl[0]; dl[1] = sl[1];
        }
        __syncthreads();

#pragma unroll
        for (int kk = 0; kk < BK; kk += 16) {
            wmma::fragment<wmma::matrix_a, 16, 16, 16, __nv_bfloat16, wmma::row_major> a[2][2];
            wmma::fragment<wmma::matrix_b, 16, 16, 16, __nv_bfloat16, wmma::row_major> b[2][4];
#pragma unroll
            for (int s = 0; s < 2; s++)
#pragma unroll
                for (int fr = 0; fr < 2; fr++)
                    wmma::load_matrix_sync(a[s][fr], &As[s][wr * 32 + fr * 16][kk], LDA);
#pragma unroll
            for (int s = 0; s < 2; s++)
#pragma unroll
                for (int fc = 0; fc < 4; fc++)
                    wmma::load_matrix_sync(b[s][fc], &Bs[s][kk][wc * 64 + fc * 16], LDB);
#pragma unroll
            for (int fr = 0; fr < 2; fr++)
#pragma unroll
                for (int fc = 0; fc < 4; fc++) {
                    wmma::mma_sync(acc[fr][fc], a[0][fr], b[0][fc], acc[fr][fc]); // hi*hi
                    wmma::mma_sync(acc[fr][fc], a[0][fr], b[1][fc], acc[fr][fc]); // hi*lo
                    wmma::mma_sync(acc[fr][fc], a[1][fr], b[0][fc], acc[fr][fc]); // lo*hi
                }
        }
        __syncthreads();
    }

#pragma unroll
    for (int fr = 0; fr < 2; fr++)
#pragma unroll
        for (int fc = 0; fc < 4; fc++)
            wmma::store_matrix_sync(C + (size_t)(m0 + wr * 32 + fr * 16) * Ndim + n0 + wc * 64 + fc * 16,
                                    acc[fr][fc], Ndim, wmma::mem_row_major);
}

// ---------------------------------------------------------------------------
// Gating: beta[b][h][t] = clip(sigmoid(x_row . Wg[:,h] + bg[h]), 0.8, 0.9995)
// One block per token row (full fp32 precision).
// ---------------------------------------------------------------------------
__global__ void gate_kernel(const float* __restrict__ x,
                            const float* __restrict__ Wg,
                            const float* __restrict__ bg)
{
    int row = blockIdx.x;            // 0..M_-1
    __shared__ float xs[HID_];
    __shared__ float red[256];
    for (int i = threadIdx.x; i < HID_; i += 256) xs[i] = x[(size_t)row * HID_ + i];
    __syncthreads();

    int h = threadIdx.x & 15;
    int kl = threadIdx.x >> 4;       // 0..15
    float acc = 0.f;
    for (int k = kl; k < HID_; k += 16) acc += xs[k] * Wg[(size_t)k * H_ + h];
    red[threadIdx.x] = acc;
    __syncthreads();
    if (threadIdx.x < 16) {
        float s = 0.f;
#pragma unroll
        for (int j = 0; j < 16; j++) s += red[threadIdx.x + 16 * j];
        float u = s + bg[threadIdx.x];
        float bv = 1.f / (1.f + expf(-u));
        bv = fminf(fmaxf(bv, 0.8f), 0.9995f);
        int b = row / L_, t = row % L_;
        g_beta[((size_t)(b * H_ + threadIdx.x)) * L_ + t] = bv;
    }
}

// ---------------------------------------------------------------------------
// RoPE + phi (elu+1) for q,k; relayout v.  One block per (b,t,h), 64 threads.
// ---------------------------------------------------------------------------
__global__ void postproc_kernel()
{
    int bid = blockIdx.x;            // B_*L_*H_
    int h  = bid % H_;
    int bt = bid / H_;
    int t  = bt % L_;
    int b  = bt / L_;
    int i  = threadIdx.x;            // 0..63
    size_t in = (size_t)bt * HID_ + h * D_;
    size_t o  = ((size_t)(b * H_ + h) * L_ + t) * D_;

    float c = g_cos[t * 64 + i], s = g_sin[t * 64 + i];

    float qe = g_q[in + i], qo = g_q[in + 64 + i];
    float ke = g_k[in + i], ko = g_k[in + 64 + i];
    float r;
    r = qe * c - qo * s;  g_pq[o + i]      = (r > 0.f) ? r + 1.f : expf(r);
    r = qe * s + qo * c;  g_pq[o + 64 + i] = (r > 0.f) ? r + 1.f : expf(r);
    r = ke * c - ko * s;  g_pk[o + i]      = (r > 0.f) ? r + 1.f : expf(r);
    r = ke * s + ko * c;  g_pk[o + 64 + i] = (r > 0.f) ? r + 1.f : expf(r);

    g_vt[o + i]      = g_v[in + i];
    g_vt[o + 64 + i] = g_v[in + 64 + i];
}

// ---------------------------------------------------------------------------
// Denominator scan: z_t = z*b + k_t ; den_t = q_t . z_t + eps
// One warp per (b,h); lane owns 4 of 128 dims (float4).
// ---------------------------------------------------------------------------
__global__ void denom_kernel()
{
    int bh = blockIdx.x;
    int lane = threadIdx.x;
    const float4* q4 = reinterpret_cast<const float4*>(g_pq) + (size_t)bh * L_ * 32;
    const float4* k4 = reinterpret_cast<const float4*>(g_pk) + (size_t)bh * L_ * 32;
    const float* bptr = g_beta + (size_t)bh * L_;
    float zx = 0.f, zy = 0.f, zz = 0.f, zw = 0.f;
    for (int t = 0; t < L_; ++t) {
        float bb = bptr[t];
        float4 kk = k4[(size_t)t * 32 + lane];
        float4 qq = q4[(size_t)t * 32 + lane];
        zx = zx * bb + kk.x; zy = zy * bb + kk.y;
        zz = zz * bb + kk.z; zw = zw * bb + kk.w;
        float p = qq.x * zx + qq.y * zy + qq.z * zz + qq.w * zw;
#pragma unroll
        for (int o = 16; o > 0; o >>= 1) p += __shfl_xor_sync(0xffffffffu, p, o);
        if (lane == 0) g_den[(size_t)bh * L_ + t] = p + 1e-6f;
    }
}

// ---------------------------------------------------------------------------
// Main state scan. e-columns of S are independent -> split each (b,h) into
// 4 e-blocks of 32 columns. 128 threads: le = e within block, hf = d-quarter.
// Thread carries S[d0..d0+31][e] in 32 registers.
// ---------------------------------------------------------------------------
__global__ void __launch_bounds__(128) scan_kernel()
{
    constexpr int NT = 8;
    int bid = blockIdx.x;            // 128 blocks
    int bh = bid >> 2;
    int ec = bid & 3;
    int b = bh / H_;
    int h = bh % H_;
    int tid = threadIdx.x;
    int le = tid & 31;               // e column within this block
    int hf = tid >> 5;               // 0..3 d-quarter
    int d0 = hf * 32;

    __shared__ float qs[NT][D_], ks[NT][D_], vs[NT][32], bs[NT], ds[NT];
    __shared__ float psum[4][32];

    const float4* pq4 = reinterpret_cast<const float4*>(g_pq) + (size_t)bh * L_ * 32;
    const float4* pk4 = reinterpret_cast<const float4*>(g_pk) + (size_t)bh * L_ * 32;
    const float4* vt4 = reinterpret_cast<const float4*>(g_vt) + (size_t)bh * L_ * 32;
    const float* bptr = g_beta + (size_t)bh * L_;
    const float* dptr = g_den  + (size_t)bh * L_;
    float* ybase = g_y + (size_t)b * L_ * HID_ + h * D_ + ec * 32;

    float S[32];
#pragma unroll
    for (int j = 0; j < 32; j++) S[j] = 0.f;

    for (int t0 = 0; t0 < L_; t0 += NT) {
        // Stage NT steps of q,k (full 128 dims) and v (our 32 cols)
        for (int id = tid; id < NT * 32; id += 128) {
            int s = id >> 5, c = id & 31;
            reinterpret_cast<float4*>(qs[s])[c] = pq4[(size_t)(t0 + s) * 32 + c];
            reinterpret_cast<float4*>(ks[s])[c] = pk4[(size_t)(t0 + s) * 32 + c];
        }
        if (tid < NT * 8) {
            int s = tid >> 3, c = tid & 7;
            reinterpret_cast<float4*>(vs[s])[c] = vt4[(size_t)(t0 + s) * 32 + ec * 8 + c];
        }
        if (tid < NT) bs[tid] = bptr[t0 + tid];
        else if (tid < 2 * NT) ds[tid - NT] = dptr[t0 + tid - NT];
        __syncthreads();

        for (int s = 0; s < NT; ++s) {
            float bb = bs[s];
            float vv = vs[s][le];
            const float4* kq = reinterpret_cast<const float4*>(&ks[s][d0]);
            const float4* qq = reinterpret_cast<const float4*>(&qs[s][d0]);
            float p0 = 0.f, p1 = 0.f, p2 = 0.f, p3 = 0.f;
#pragma unroll
            for (int j = 0; j < 8; j++) {
                float4 kf = kq[j];
                float4 qf = qq[j];
                S[4*j+0] = S[4*j+0] * bb + kf.x * vv; p0 += qf.x * S[4*j+0];
                S[4*j+1] = S[4*j+1] * bb + kf.y * vv; p1 += qf.y * S[4*j+1];
                S[4*j+2] = S[4*j+2] * bb + kf.z * vv; p2 += qf.z * S[4*j+2];
                S[4*j+3] = S[4*j+3] * bb + kf.w * vv; p3 += qf.w * S[4*j+3];
            }
            float p = (p0 + p1) + (p2 + p3);
            if (hf) psum[hf][le] = p;
            __syncthreads();
            if (hf == 0) {
                float tot = p + psum[1][le] + psum[2][le] + psum[3][le];
                ybase[(size_t)(t0 + s) * HID_ + le] = tot / ds[s];
            }
            __syncthreads();
        }
    }
}

// ---------------------------------------------------------------------------
// Bias add on final output
// ---------------------------------------------------------------------------
__global__ void bias_kernel(float* __restrict__ out, const float* __restrict__ bo, int n)
{
    int i = blockIdx.x * blockDim.x + threadIdx.x;
    if (i < n) out[i] += bo[i & (HID_ - 1)];
}

// ---------------------------------------------------------------------------
// Launch
// ---------------------------------------------------------------------------
extern "C" void kernel_launch(void* const* d_in, const int* in_sizes, int n_in,
                              void* d_out, int out_size)
{
    const float* x  = (const float*)d_in[0];
    const float* Wq = (const float*)d_in[1];
    const float* Wk = (const float*)d_in[2];
    const float* Wv = (const float*)d_in[3];
    const float* Wg = (const float*)d_in[4];
    const float* bg = (const float*)d_in[5];
    const float* Wo = (const float*)d_in[6];
    const float* bo = (const float*)d_in[7];
    float* out = (float*)d_out;

    void* p;
    __nv_bfloat16 *xh, *xl, *wh, *wl, *yh, *yl;
    float *qf, *kf, *vf, *yf;
    cudaGetSymbolAddress(&p, g_xh); xh = (__nv_bfloat16*)p;
    cudaGetSymbolAddress(&p, g_xl); xl = (__nv_bfloat16*)p;
    cudaGetSymbolAddress(&p, g_wh); wh = (__nv_bfloat16*)p;
    cudaGetSymbolAddress(&p, g_wl); wl = (__nv_bfloat16*)p;
    cudaGetSymbolAddress(&p, g_yh); yh = (__nv_bfloat16*)p;
    cudaGetSymbolAddress(&p, g_yl); yl = (__nv_bfloat16*)p;
    cudaGetSymbolAddress(&p, g_q);  qf = (float*)p;
    cudaGetSymbolAddress(&p, g_k);  kf = (float*)p;
    cudaGetSymbolAddress(&p, g_v);  vf = (float*)p;
    cudaGetSymbolAddress(&p, g_y);  yf = (float*)p;

    const int NX = M_ * HID_;
    const size_t NW = (size_t)HID_ * HID_;

    // 1) splits of x and all weights
    split_kernel<<<(NX + 255) / 256, 256>>>(x,  xh, xl, NX);
    split_kernel<<<((int)NW + 255) / 256, 256>>>(Wq, wh + 0 * NW, wl + 0 * NW, (int)NW);
    split_kernel<<<((int)NW + 255) / 256, 256>>>(Wk, wh + 1 * NW, wl + 1 * NW, (int)NW);
    split_kernel<<<((int)NW + 255) / 256, 256>>>(Wv, wh + 2 * NW, wl + 2 * NW, (int)NW);
    split_kernel<<<((int)NW + 255) / 256, 256>>>(Wo, wh + 3 * NW, wl + 3 * NW, (int)NW);
    rope_table_kernel<<<L_, 64>>>();

    // 2) projection GEMMs
    dim3 gg(HID_ / 128, M_ / 128);
    gemm_split_kernel<<<gg, 256>>>(xh, xl, wh + 0 * NW, wl + 0 * NW, qf, M_, HID_, HID_);
    gemm_split_kernel<<<gg, 256>>>(xh, xl, wh + 1 * NW, wl + 1 * NW, kf, M_, HID_, HID_);
    gemm_split_kernel<<<gg, 256>>>(xh, xl, wh + 2 * NW, wl + 2 * NW, vf, M_, HID_, HID_);

    // 3) gating + rope/phi/relayout
    gate_kernel<<<M_, 256>>>(x, Wg, bg);
    postproc_kernel<<<B_ * L_ * H_, 64>>>();

    // 4) scans
    denom_kernel<<<B_ * H_, 32>>>();
    scan_kernel<<<B_ * H_ * 4, 128>>>();

    // 5) output projection + bias
    split_kernel<<<(NX + 255) / 256, 256>>>(yf, yh, yl, NX);
    gemm_split_kernel<<<gg, 256>>>(yh, yl, wh + 3 * NW, wl + 3 * NW, out, M_, HID_, HID_);
    bias_kernel<<<(NX + 255) / 256, 256>>>(out, bo, NX);
}

// round 7
// speedup vs baseline: 1.2096x; 1.2096x over previous
#include <cuda_runtime.h>
#include <cuda_bf16.h>
#include <mma.h>
#include <math.h>
#include <stdint.h>

using namespace nvcuda;

// Problem constants
constexpr int B_   = 2;
constexpr int L_   = 2048;
constexpr int HID_ = 2048;
constexpr int H_   = 16;
constexpr int D_   = 128;
constexpr int M_   = B_ * L_;      // 4096 token rows
constexpr int BHL_ = B_ * H_ * L_;

// ---------------------------------------------------------------------------
// Static scratch (no cudaMalloc allowed)
// ---------------------------------------------------------------------------
__device__ __align__(16) __nv_bfloat16 g_xh[M_ * HID_];
__device__ __align__(16) __nv_bfloat16 g_xl[M_ * HID_];
__device__ __align__(16) __nv_bfloat16 g_wh[4][(size_t)HID_ * HID_];  // [K][N] row-major
__device__ __align__(16) __nv_bfloat16 g_wl[4][(size_t)HID_ * HID_];
__device__ __align__(16) float g_q[M_ * HID_];
__device__ __align__(16) float g_k[M_ * HID_];
__device__ __align__(16) float g_v[M_ * HID_];
__device__ __align__(16) float g_pq[M_ * HID_];   // phi(rope(q)) [b][h][t][d]
__device__ __align__(16) float g_pk[M_ * HID_];
__device__ __align__(16) float g_vt[M_ * HID_];
__device__ __align__(16) float g_beta[BHL_];
__device__ __align__(16) float g_den[BHL_];
__device__ __align__(16) float g_y[M_ * HID_];
__device__ __align__(16) __nv_bfloat16 g_yh[M_ * HID_];
__device__ __align__(16) __nv_bfloat16 g_yl[M_ * HID_];
__device__ __align__(16) float g_cos[L_ * 64];
__device__ __align__(16) float g_sin[L_ * 64];

// ---------------------------------------------------------------------------
// PTX helpers (cp.async only — tcgen05 is NOT available: harness lowers to
// .target sm_103 without the 'a' suffix, so arch-accelerated features fail)
// ---------------------------------------------------------------------------
__device__ __forceinline__ uint32_t smem_u32(const void* p) {
    uint32_t a;
    asm("{ .reg .u64 t; cvta.to.shared.u64 t, %1; cvt.u32.u64 %0, t; }"
        : "=r"(a) : "l"(p));
    return a;
}
__device__ __forceinline__ void cp_async16(uint32_t dst, const void* src) {
    asm volatile("cp.async.cg.shared.global [%0], [%1], 16;" :: "r"(dst), "l"(src));
}
__device__ __forceinline__ void cp_commit() {
    asm volatile("cp.async.commit_group;" ::: "memory");
}
template<int N> __device__ __forceinline__ void cp_wait() {
    asm volatile("cp.async.wait_group %0;" :: "n"(N) : "memory");
}

// ---------------------------------------------------------------------------
// fp32 -> (hi, lo) bf16 split
// ---------------------------------------------------------------------------
__global__ void split_kernel(const float* __restrict__ x,
                             __nv_bfloat16* __restrict__ hi,
                             __nv_bfloat16* __restrict__ lo, int n)
{
    int i = blockIdx.x * blockDim.x + threadIdx.x;
    if (i < n) {
        float v = x[i];
        __nv_bfloat16 h = __float2bfloat16(v);
        hi[i] = h;
        lo[i] = __float2bfloat16(v - __bfloat162float(h));
    }
}

// ---------------------------------------------------------------------------
// RoPE table
// ---------------------------------------------------------------------------
__global__ void rope_table_kernel()
{
    int t = blockIdx.x;
    int i = threadIdx.x;           // 0..63
    double inv = pow(10000.0, -(double)i / 64.0);
    float invf = (float)inv;
    float f = (float)t * invf;
    g_cos[t * 64 + i] = cosf(f);
    g_sin[t * 64 + i] = sinf(f);
}

// ---------------------------------------------------------------------------
// Split-bf16 GEMM with 4-stage cp.async pipeline.
// C = A @ B, A [M,K] row-major, B [K,N] row-major, C [M,N] fp32.
// 128x128 tile, BK=32, 8 warps (4x2), warp tile 32x64.
// fp32-equivalent via hi*hi + hi*lo + lo*hi.
// ---------------------------------------------------------------------------
constexpr int BM = 128, BN = 128, BK = 32;
constexpr int STAGES = 4;
constexpr int LDA = 40;                 // halves (80B row stride, 16B multiple)
constexpr int LDB = 136;                // halves (272B row stride, 16B multiple)
constexpr int A_SPLIT_B = BM * LDA * 2; // 10240
constexpr int B_SPLIT_B = BK * LDB * 2; // 8704
constexpr int A_TOT_B   = 2 * A_SPLIT_B;               // 20480
constexpr int STAGE_B   = A_TOT_B + 2 * B_SPLIT_B;     // 37888
constexpr int GEMM_SMEM = STAGES * STAGE_B;            // 151552 (~148KB)

__device__ __forceinline__ void gemm_load_slab(
    uint32_t sbase, int stage, int tid, int m0, int n0, int k0,
    const __nv_bfloat16* __restrict__ Ah, const __nv_bfloat16* __restrict__ Al,
    const __nv_bfloat16* __restrict__ Bh, const __nv_bfloat16* __restrict__ Bl)
{
    uint32_t st = sbase + (uint32_t)stage * STAGE_B;
    // A: 2 splits x 128 rows x 4 chunks(16B) = 1024 chunks, 4/thread
#pragma unroll
    for (int i = 0; i < 4; i++) {
        int id = tid + i * 256;
        const __nv_bfloat16* base = (id & 512) ? Al : Ah;
        uint32_t off = (id & 512) ? (uint32_t)A_SPLIT_B : 0u;
        int r = (id >> 2) & 127;
        int j = id & 3;
        cp_async16(st + off + r * 80 + j * 16,
                   base + (size_t)(m0 + r) * HID_ + k0 + j * 8);
    }
    // B: 2 splits x 32 rows x 16 chunks = 1024 chunks, 4/thread
#pragma unroll
    for (int i = 0; i < 4; i++) {
        int id = tid + i * 256;
        const __nv_bfloat16* base = (id & 512) ? Bl : Bh;
        uint32_t off = (uint32_t)A_TOT_B + ((id & 512) ? (uint32_t)B_SPLIT_B : 0u);
        int r = (id >> 4) & 31;
        int j = id & 15;
        cp_async16(st + off + r * 272 + j * 16,
                   base + (size_t)(k0 + r) * HID_ + n0 + j * 8);
    }
    cp_commit();
}

__global__ void __launch_bounds__(256, 1)
gemm_split_pipe(const __nv_bfloat16* __restrict__ Ah, const __nv_bfloat16* __restrict__ Al,
                const __nv_bfloat16* __restrict__ Bh, const __nv_bfloat16* __restrict__ Bl,
                float* __restrict__ C)
{
    extern __shared__ __align__(16) char smem[];

    const int tid = threadIdx.x;
    const int wid = tid >> 5;
    const int wr  = wid >> 1;   // 0..3
    const int wc  = wid & 1;    // 0..1
    const int m0  = blockIdx.y * BM;
    const int n0  = blockIdx.x * BN;

    uint32_t sbase = smem_u32(smem);

    wmma::fragment<wmma::accumulator, 16, 16, 16, float> acc[2][4];
#pragma unroll
    for (int i = 0; i < 2; i++)
#pragma unroll
        for (int j = 0; j < 4; j++) wmma::fill_fragment(acc[i][j], 0.0f);

    constexpr int NI = HID_ / BK;   // 64

    // prologue: fill STAGES-1 slabs
#pragma unroll
    for (int s = 0; s < STAGES - 1; s++)
        gemm_load_slab(sbase, s, tid, m0, n0, s * BK, Ah, Al, Bh, Bl);

#pragma unroll 1
    for (int i = 0; i < NI; i++) {
        if (i + STAGES - 1 < NI) cp_wait<STAGES - 2>();
        else                     cp_wait<0>();
        __syncthreads();

        // refill the slab consumed at iteration i-1
        if (i + STAGES - 1 < NI)
            gemm_load_slab(sbase, (i + STAGES - 1) % STAGES, tid, m0, n0,
                           (i + STAGES - 1) * BK, Ah, Al, Bh, Bl);

        const char* st = smem + (size_t)(i % STAGES) * STAGE_B;
        const __nv_bfloat16* As0 = (const __nv_bfloat16*)(st);
        const __nv_bfloat16* As1 = (const __nv_bfloat16*)(st + A_SPLIT_B);
        const __nv_bfloat16* Bs0 = (const __nv_bfloat16*)(st + A_TOT_B);
        const __nv_bfloat16* Bs1 = (const __nv_bfloat16*)(st + A_TOT_B + B_SPLIT_B);

#pragma unroll
        for (int kk = 0; kk < BK; kk += 16) {
            wmma::fragment<wmma::matrix_a, 16, 16, 16, __nv_bfloat16, wmma::row_major> a[2][2];
            wmma::fragment<wmma::matrix_b, 16, 16, 16, __nv_bfloat16, wmma::row_major> b[2][4];
#pragma unroll
            for (int fr = 0; fr < 2; fr++) {
                wmma::load_matrix_sync(a[0][fr], As0 + (wr * 32 + fr * 16) * LDA + kk, LDA);
                wmma::load_matrix_sync(a[1][fr], As1 + (wr * 32 + fr * 16) * LDA + kk, LDA);
            }
#pragma unroll
            for (int fc = 0; fc < 4; fc++) {
                wmma::load_matrix_sync(b[0][fc], Bs0 + kk * LDB + wc * 64 + fc * 16, LDB);
                wmma::load_matrix_sync(b[1][fc], Bs1 + kk * LDB + wc * 64 + fc * 16, LDB);
            }
#pragma unroll
            for (int fr = 0; fr < 2; fr++)
#pragma unroll
                for (int fc = 0; fc < 4; fc++) {
                    wmma::mma_sync(acc[fr][fc], a[0][fr], b[0][fc], acc[fr][fc]); // hi*hi
                    wmma::mma_sync(acc[fr][fc], a[0][fr], b[1][fc], acc[fr][fc]); // hi*lo
                    wmma::mma_sync(acc[fr][fc], a[1][fr], b[0][fc], acc[fr][fc]); // lo*hi
                }
        }
        __syncthreads();
    }

#pragma unroll
    for (int fr = 0; fr < 2; fr++)
#pragma unroll
        for (int fc = 0; fc < 4; fc++)
            wmma::store_matrix_sync(C + (size_t)(m0 + wr * 32 + fr * 16) * HID_ + n0 + wc * 64 + fc * 16,
                                    acc[fr][fc], HID_, wmma::mem_row_major);
}

// ---------------------------------------------------------------------------
// Gating: beta[b][h][t] = clip(sigmoid(x_row . Wg[:,h] + bg[h]), 0.8, 0.9995)
// ---------------------------------------------------------------------------
__global__ void gate_kernel(const float* __restrict__ x,
                            const float* __restrict__ Wg,
                            const float* __restrict__ bg)
{
    int row = blockIdx.x;
    __shared__ float xs[HID_];
    __shared__ float red[256];
    for (int i = threadIdx.x; i < HID_; i += 256) xs[i] = x[(size_t)row * HID_ + i];
    __syncthreads();

    int h = threadIdx.x & 15;
    int kl = threadIdx.x >> 4;
    float acc = 0.f;
    for (int k = kl; k < HID_; k += 16) acc += xs[k] * Wg[(size_t)k * H_ + h];
    red[threadIdx.x] = acc;
    __syncthreads();
    if (threadIdx.x < 16) {
        float s = 0.f;
#pragma unroll
        for (int j = 0; j < 16; j++) s += red[threadIdx.x + 16 * j];
        float u = s + bg[threadIdx.x];
        float bv = 1.f / (1.f + expf(-u));
        bv = fminf(fmaxf(bv, 0.8f), 0.9995f);
        int b = row / L_, t = row % L_;
        g_beta[((size_t)(b * H_ + threadIdx.x)) * L_ + t] = bv;
    }
}

// ---------------------------------------------------------------------------
// RoPE + phi for q,k; relayout v.
// ---------------------------------------------------------------------------
__global__ void postproc_kernel()
{
    int bid = blockIdx.x;
    int h  = bid % H_;
    int bt = bid / H_;
    int t  = bt % L_;
    int b  = bt / L_;
    int i  = threadIdx.x;            // 0..63
    size_t in = (size_t)bt * HID_ + h * D_;
    size_t o  = ((size_t)(b * H_ + h) * L_ + t) * D_;

    float c = g_cos[t * 64 + i], s = g_sin[t * 64 + i];

    float qe = g_q[in + i], qo = g_q[in + 64 + i];
    float ke = g_k[in + i], ko = g_k[in + 64 + i];
    float r;
    r = qe * c - qo * s;  g_pq[o + i]      = (r > 0.f) ? r + 1.f : expf(r);
    r = qe * s + qo * c;  g_pq[o + 64 + i] = (r > 0.f) ? r + 1.f : expf(r);
    r = ke * c - ko * s;  g_pk[o + i]      = (r > 0.f) ? r + 1.f : expf(r);
    r = ke * s + ko * c;  g_pk[o + 64 + i] = (r > 0.f) ? r + 1.f : expf(r);

    g_vt[o + i]      = g_v[in + i];
    g_vt[o + 64 + i] = g_v[in + 64 + i];
}

// ---------------------------------------------------------------------------
// Denominator scan: z = z*b + k ; den = q.z + eps.
// One warp per (b,h); per-lane partials staged to smem, one reduce per 32 t.
// ---------------------------------------------------------------------------
__global__ void __launch_bounds__(32) denom_kernel()
{
    int bh = blockIdx.x;
    int lane = threadIdx.x;
    __shared__ float ps[32][33];
    const float4* q4 = reinterpret_cast<const float4*>(g_pq) + (size_t)bh * L_ * 32;
    const float4* k4 = reinterpret_cast<const float4*>(g_pk) + (size_t)bh * L_ * 32;
    const float* bptr = g_beta + (size_t)bh * L_;
    float* dptr = g_den + (size_t)bh * L_;
    float zx = 0.f, zy = 0.f, zz = 0.f, zw = 0.f;
    for (int t0 = 0; t0 < L_; t0 += 32) {
#pragma unroll 8
        for (int i = 0; i < 32; i++) {
            int t = t0 + i;
            float bb = bptr[t];
            float4 kk = k4[(size_t)t * 32 + lane];
            float4 qq = q4[(size_t)t * 32 + lane];
            zx = zx * bb + kk.x; zy = zy * bb + kk.y;
            zz = zz * bb + kk.z; zw = zw * bb + kk.w;
            ps[i][lane] = qq.x * zx + qq.y * zy + qq.z * zz + qq.w * zw;
        }
        __syncwarp();
        float acc = 0.f;
#pragma unroll
        for (int j = 0; j < 32; j++) acc += ps[lane][j];
        dptr[t0 + lane] = acc + 1e-6f;
        __syncwarp();
    }
}

// ---------------------------------------------------------------------------
// Main state scan. 4 e-blocks of 32 cols per (b,h). Thread (le, hf):
// le = tid>>2 (e col), hf = tid&3 (d quarter) -> partner lanes adjacent,
// reduction via 2x shfl.xor (no per-step barriers).
// ---------------------------------------------------------------------------
__global__ void __launch_bounds__(128) scan_kernel()
{
    constexpr int NT = 16;
    int bid = blockIdx.x;            // 128 blocks
    int bh = bid >> 2;
    int ec = bid & 3;
    int b = bh / H_;
    int h = bh % H_;
    int tid = threadIdx.x;
    int le = tid >> 2;               // 0..31 e column within block
    int hf = tid & 3;                // 0..3 d-quarter
    int d0 = hf * 32;

    __shared__ float qs[NT][D_], ks[NT][D_], vs[NT][32], bs[NT], ds[NT];

    const float4* pq4 = reinterpret_cast<const float4*>(g_pq) + (size_t)bh * L_ * 32;
    const float4* pk4 = reinterpret_cast<const float4*>(g_pk) + (size_t)bh * L_ * 32;
    const float4* vt4 = reinterpret_cast<const float4*>(g_vt) + (size_t)bh * L_ * 32;
    const float* bptr = g_beta + (size_t)bh * L_;
    const float* dptr = g_den  + (size_t)bh * L_;
    float* ybase = g_y + (size_t)b * L_ * HID_ + h * D_ + ec * 32;

    float S[32];
#pragma unroll
    for (int j = 0; j < 32; j++) S[j] = 0.f;

    for (int t0 = 0; t0 < L_; t0 += NT) {
#pragma unroll
        for (int id = tid; id < NT * 32; id += 128) {
            int s = id >> 5, c = id & 31;
            reinterpret_cast<float4*>(qs[s])[c] = pq4[(size_t)(t0 + s) * 32 + c];
            reinterpret_cast<float4*>(ks[s])[c] = pk4[(size_t)(t0 + s) * 32 + c];
        }
        {
            int s = tid >> 3, c = tid & 7;   // NT*8 == 128
            reinterpret_cast<float4*>(vs[s])[c] = vt4[(size_t)(t0 + s) * 32 + ec * 8 + c];
        }
        if (tid < NT) bs[tid] = bptr[t0 + tid];
        else if (tid < 2 * NT) ds[tid - NT] = dptr[t0 + tid - NT];
        __syncthreads();

#pragma unroll 1
        for (int s = 0; s < NT; ++s) {
            float bb = bs[s];
            float vv = vs[s][le];
            const float4* kq = reinterpret_cast<const float4*>(&ks[s][d0]);
            const float4* qq = reinterpret_cast<const float4*>(&qs[s][d0]);
            float p0 = 0.f, p1 = 0.f, p2 = 0.f, p3 = 0.f;
#pragma unroll
            for (int j = 0; j < 8; j++) {
                float4 kf = kq[j];
                float4 qf = qq[j];
                S[4*j+0] = S[4*j+0] * bb + kf.x * vv; p0 += qf.x * S[4*j+0];
                S[4*j+1] = S[4*j+1] * bb + kf.y * vv; p1 += qf.y * S[4*j+1];
                S[4*j+2] = S[4*j+2] * bb + kf.z * vv; p2 += qf.z * S[4*j+2];
                S[4*j+3] = S[4*j+3] * bb + kf.w * vv; p3 += qf.w * S[4*j+3];
            }
            float p = (p0 + p1) + (p2 + p3);
            p += __shfl_xor_sync(0xffffffffu, p, 1);
            p += __shfl_xor_sync(0xffffffffu, p, 2);
            if (hf == 0) ybase[(size_t)(t0 + s) * HID_ + le] = p / ds[s];
        }
        __syncthreads();
    }
}

// ---------------------------------------------------------------------------
// Bias add on final output
// ---------------------------------------------------------------------------
__global__ void bias_kernel(float* __restrict__ out, const float* __restrict__ bo, int n)
{
    int i = blockIdx.x * blockDim.x + threadIdx.x;
    if (i < n) out[i] += bo[i & (HID_ - 1)];
}

// ---------------------------------------------------------------------------
// Launch
// ---------------------------------------------------------------------------
extern "C" void kernel_launch(void* const* d_in, const int* in_sizes, int n_in,
                              void* d_out, int out_size)
{
    const float* x  = (const float*)d_in[0];
    const float* Wq = (const float*)d_in[1];
    const float* Wk = (const float*)d_in[2];
    const float* Wv = (const float*)d_in[3];
    const float* Wg = (const float*)d_in[4];
    const float* bg = (const float*)d_in[5];
    const float* Wo = (const float*)d_in[6];
    const float* bo = (const float*)d_in[7];
    float* out = (float*)d_out;

    void* p;
    __nv_bfloat16 *xh, *xl, *wh, *wl, *yh, *yl;
    float *qf, *kf, *vf, *yf;
    cudaGetSymbolAddress(&p, g_xh); xh = (__nv_bfloat16*)p;
    cudaGetSymbolAddress(&p, g_xl); xl = (__nv_bfloat16*)p;
    cudaGetSymbolAddress(&p, g_wh); wh = (__nv_bfloat16*)p;
    cudaGetSymbolAddress(&p, g_wl); wl = (__nv_bfloat16*)p;
    cudaGetSymbolAddress(&p, g_yh); yh = (__nv_bfloat16*)p;
    cudaGetSymbolAddress(&p, g_yl); yl = (__nv_bfloat16*)p;
    cudaGetSymbolAddress(&p, g_q);  qf = (float*)p;
    cudaGetSymbolAddress(&p, g_k);  kf = (float*)p;
    cudaGetSymbolAddress(&p, g_v);  vf = (float*)p;
    cudaGetSymbolAddress(&p, g_y);  yf = (float*)p;

    cudaFuncSetAttribute(gemm_split_pipe, cudaFuncAttributeMaxDynamicSharedMemorySize, GEMM_SMEM);

    const int NX = M_ * HID_;
    const size_t NW = (size_t)HID_ * HID_;

    // 1) splits of x and all weights
    split_kernel<<<(NX + 255) / 256, 256>>>(x,  xh, xl, NX);
    split_kernel<<<((int)NW + 255) / 256, 256>>>(Wq, wh + 0 * NW, wl + 0 * NW, (int)NW);
    split_kernel<<<((int)NW + 255) / 256, 256>>>(Wk, wh + 1 * NW, wl + 1 * NW, (int)NW);
    split_kernel<<<((int)NW + 255) / 256, 256>>>(Wv, wh + 2 * NW, wl + 2 * NW, (int)NW);
    split_kernel<<<((int)NW + 255) / 256, 256>>>(Wo, wh + 3 * NW, wl + 3 * NW, (int)NW);
    rope_table_kernel<<<L_, 64>>>();

    // 2) projection GEMMs (pipelined)
    dim3 gg(HID_ / BN, M_ / BM);   // (16, 32)
    gemm_split_pipe<<<gg, 256, GEMM_SMEM>>>(xh, xl, wh + 0 * NW, wl + 0 * NW, qf);
    gemm_split_pipe<<<gg, 256, GEMM_SMEM>>>(xh, xl, wh + 1 * NW, wl + 1 * NW, kf);
    gemm_split_pipe<<<gg, 256, GEMM_SMEM>>>(xh, xl, wh + 2 * NW, wl + 2 * NW, vf);

    // 3) gating + rope/phi/relayout
    gate_kernel<<<M_, 256>>>(x, Wg, bg);
    postproc_kernel<<<B_ * L_ * H_, 64>>>();

    // 4) scans
    denom_kernel<<<B_ * H_, 32>>>();
    scan_kernel<<<B_ * H_ * 4, 128>>>();

    // 5) output projection + bias
    split_kernel<<<(NX + 255) / 256, 256>>>(yf, yh, yl, NX);
    gemm_split_pipe<<<gg, 256, GEMM_SMEM>>>(yh, yl, wh + 3 * NW, wl + 3 * NW, out);
    bias_kernel<<<(NX + 255) / 256, 256>>>(out, bo, NX);
}

// round 8
// speedup vs baseline: 1.3315x; 1.1008x over previous
#include <cuda_runtime.h>
#include <cuda_bf16.h>
#include <mma.h>
#include <math.h>
#include <stdint.h>

using namespace nvcuda;

// Problem constants
constexpr int B_   = 2;
constexpr int L_   = 2048;
constexpr int HID_ = 2048;
constexpr int H_   = 16;
constexpr int D_   = 128;
constexpr int M_   = B_ * L_;      // 4096 token rows
constexpr int BHL_ = B_ * H_ * L_;

// ---------------------------------------------------------------------------
// Static scratch (no cudaMalloc allowed)
// ---------------------------------------------------------------------------
__device__ __align__(16) __nv_bfloat16 g_xh[M_ * HID_];
__device__ __align__(16) __nv_bfloat16 g_xl[M_ * HID_];
__device__ __align__(16) __nv_bfloat16 g_wh[4][(size_t)HID_ * HID_];  // [K][N] row-major
__device__ __align__(16) __nv_bfloat16 g_wl[4][(size_t)HID_ * HID_];
__device__ __align__(16) float g_q[M_ * HID_];
__device__ __align__(16) float g_k[M_ * HID_];
__device__ __align__(16) float g_v[M_ * HID_];
__device__ __align__(16) float g_pq[M_ * HID_];   // phi(rope(q)) [b][h][t][d]
__device__ __align__(16) float g_pk[M_ * HID_];
__device__ __align__(16) float g_vt[M_ * HID_];
__device__ __align__(16) float g_beta[BHL_];
__device__ __align__(16) float g_den[BHL_];
__device__ __align__(16) float g_y[M_ * HID_];
__device__ __align__(16) __nv_bfloat16 g_yh[M_ * HID_];
__device__ __align__(16) __nv_bfloat16 g_yl[M_ * HID_];
__device__ __align__(16) float g_cos[L_ * 64];
__device__ __align__(16) float g_sin[L_ * 64];

// ---------------------------------------------------------------------------
// PTX helpers (cp.async only — tcgen05 not available: harness lowers to
// .target sm_103 without the 'a' suffix)
// ---------------------------------------------------------------------------
__device__ __forceinline__ uint32_t smem_u32(const void* p) {
    uint32_t a;
    asm("{ .reg .u64 t; cvta.to.shared.u64 t, %1; cvt.u32.u64 %0, t; }"
        : "=r"(a) : "l"(p));
    return a;
}
__device__ __forceinline__ void cp_async16(uint32_t dst, const void* src) {
    asm volatile("cp.async.cg.shared.global [%0], [%1], 16;" :: "r"(dst), "l"(src));
}
__device__ __forceinline__ void cp_commit() {
    asm volatile("cp.async.commit_group;" ::: "memory");
}
template<int N> __device__ __forceinline__ void cp_wait() {
    asm volatile("cp.async.wait_group %0;" :: "n"(N) : "memory");
}

// ---------------------------------------------------------------------------
// fp32 -> (hi, lo) bf16 split, 8 elements/thread (16B stores)
// ---------------------------------------------------------------------------
__global__ void split_kernel(const float* __restrict__ x,
                             __nv_bfloat16* __restrict__ hi,
                             __nv_bfloat16* __restrict__ lo, int n)
{
    int i = (blockIdx.x * blockDim.x + threadIdx.x) * 8;
    if (i < n) {
        float4 a = *reinterpret_cast<const float4*>(x + i);
        float4 b = *reinterpret_cast<const float4*>(x + i + 4);
        float vv[8] = {a.x, a.y, a.z, a.w, b.x, b.y, b.z, b.w};
        __nv_bfloat16 h[8], l[8];
#pragma unroll
        for (int j = 0; j < 8; j++) {
            h[j] = __float2bfloat16(vv[j]);
            l[j] = __float2bfloat16(vv[j] - __bfloat162float(h[j]));
        }
        *reinterpret_cast<uint4*>(hi + i) = *reinterpret_cast<uint4*>(h);
        *reinterpret_cast<uint4*>(lo + i) = *reinterpret_cast<uint4*>(l);
    }
}

// ---------------------------------------------------------------------------
// RoPE table
// ---------------------------------------------------------------------------
__global__ void rope_table_kernel()
{
    int t = blockIdx.x;
    int i = threadIdx.x;           // 0..63
    double inv = pow(10000.0, -(double)i / 64.0);
    float invf = (float)inv;
    float f = (float)t * invf;
    g_cos[t * 64 + i] = cosf(f);
    g_sin[t * 64 + i] = sinf(f);
}

// ---------------------------------------------------------------------------
// Split-bf16 GEMM, 3-stage cp.async pipeline.
// C = A @ B, A [M,K] row-major, B [K,N] row-major, C [M,N] fp32.
// CTA tile 128x256, BK=32. 8 warps (2x4), warp tile 64x64 (4x4 frags).
// fp32-equivalent via hi*hi + hi*lo + lo*hi.
// ---------------------------------------------------------------------------
constexpr int BM = 128, BN = 256, BK = 32;
constexpr int STAGES = 3;
constexpr int LDA = 40;                  // halves: 80B row stride
constexpr int LDB = 264;                 // halves: 528B row stride
constexpr int A_SPLIT_B = BM * LDA * 2;  // 10240
constexpr int B_SPLIT_B = BK * LDB * 2;  // 16896
constexpr int A_TOT_B   = 2 * A_SPLIT_B;              // 20480
constexpr int STAGE_B   = A_TOT_B + 2 * B_SPLIT_B;    // 54272
constexpr int GEMM_SMEM = STAGES * STAGE_B;           // 162816 (~159KB)

__device__ __forceinline__ void gemm_load_slab(
    uint32_t sbase, int stage, int tid, int m0, int n0, int k0,
    const __nv_bfloat16* __restrict__ Ah, const __nv_bfloat16* __restrict__ Al,
    const __nv_bfloat16* __restrict__ Bh, const __nv_bfloat16* __restrict__ Bl)
{
    uint32_t st = sbase + (uint32_t)stage * STAGE_B;
    // A: 2 splits x 128 rows x 4 chunks(16B) = 1024 chunks, 4/thread
#pragma unroll
    for (int i = 0; i < 4; i++) {
        int id = tid + i * 256;
        const __nv_bfloat16* base = (id & 512) ? Al : Ah;
        uint32_t off = (id & 512) ? (uint32_t)A_SPLIT_B : 0u;
        int r = (id >> 2) & 127;
        int j = id & 3;
        cp_async16(st + off + r * 80 + j * 16,
                   base + (size_t)(m0 + r) * HID_ + k0 + j * 8);
    }
    // B: 2 splits x 32 rows x 32 chunks = 2048 chunks, 8/thread
#pragma unroll
    for (int i = 0; i < 8; i++) {
        int id = tid + i * 256;
        const __nv_bfloat16* base = (id & 1024) ? Bl : Bh;
        uint32_t off = (uint32_t)A_TOT_B + ((id & 1024) ? (uint32_t)B_SPLIT_B : 0u);
        int r = (id >> 5) & 31;
        int j = id & 31;
        cp_async16(st + off + r * 528 + j * 16,
                   base + (size_t)(k0 + r) * HID_ + n0 + j * 8);
    }
    cp_commit();
}

__global__ void __launch_bounds__(256, 1)
gemm_split_pipe(const __nv_bfloat16* __restrict__ Ah, const __nv_bfloat16* __restrict__ Al,
                const __nv_bfloat16* __restrict__ Bh, const __nv_bfloat16* __restrict__ Bl,
                float* __restrict__ C)
{
    extern __shared__ __align__(16) char smem[];

    const int tid = threadIdx.x;
    const int wid = tid >> 5;
    const int wr  = wid >> 2;   // 0..1  (64-row strip)
    const int wc  = wid & 3;    // 0..3  (64-col strip)
    const int m0  = blockIdx.y * BM;
    const int n0  = blockIdx.x * BN;

    uint32_t sbase = smem_u32(smem);

    wmma::fragment<wmma::accumulator, 16, 16, 16, float> acc[4][4];
#pragma unroll
    for (int i = 0; i < 4; i++)
#pragma unroll
        for (int j = 0; j < 4; j++) wmma::fill_fragment(acc[i][j], 0.0f);

    constexpr int NI = HID_ / BK;   // 64

    // prologue: fill STAGES-1 slabs
#pragma unroll
    for (int s = 0; s < STAGES - 1; s++)
        gemm_load_slab(sbase, s, tid, m0, n0, s * BK, Ah, Al, Bh, Bl);

#pragma unroll 1
    for (int i = 0; i < NI; i++) {
        if (i + STAGES - 1 < NI) cp_wait<STAGES - 2>();
        else                     cp_wait<0>();
        __syncthreads();   // slab i visible to all; all threads done with slab i-1

        // refill the slab consumed at iteration i-1
        if (i + STAGES - 1 < NI)
            gemm_load_slab(sbase, (i + STAGES - 1) % STAGES, tid, m0, n0,
                           (i + STAGES - 1) * BK, Ah, Al, Bh, Bl);

        const char* st = smem + (size_t)(i % STAGES) * STAGE_B;
        const __nv_bfloat16* As0 = (const __nv_bfloat16*)(st);
        const __nv_bfloat16* As1 = (const __nv_bfloat16*)(st + A_SPLIT_B);
        const __nv_bfloat16* Bs0 = (const __nv_bfloat16*)(st + A_TOT_B);
        const __nv_bfloat16* Bs1 = (const __nv_bfloat16*)(st + A_TOT_B + B_SPLIT_B);

#pragma unroll
        for (int kk = 0; kk < BK; kk += 16) {
            wmma::fragment<wmma::matrix_b, 16, 16, 16, __nv_bfloat16, wmma::row_major> b0[4], b1[4];
#pragma unroll
            for (int fc = 0; fc < 4; fc++) {
                wmma::load_matrix_sync(b0[fc], Bs0 + kk * LDB + wc * 64 + fc * 16, LDB);
                wmma::load_matrix_sync(b1[fc], Bs1 + kk * LDB + wc * 64 + fc * 16, LDB);
            }
#pragma unroll
            for (int fr = 0; fr < 4; fr++) {
                wmma::fragment<wmma::matrix_a, 16, 16, 16, __nv_bfloat16, wmma::row_major> a0, a1;
                wmma::load_matrix_sync(a0, As0 + (wr * 64 + fr * 16) * LDA + kk, LDA);
                wmma::load_matrix_sync(a1, As1 + (wr * 64 + fr * 16) * LDA + kk, LDA);
#pragma unroll
                for (int fc = 0; fc < 4; fc++) {
                    wmma::mma_sync(acc[fr][fc], a0, b0[fc], acc[fr][fc]); // hi*hi
                    wmma::mma_sync(acc[fr][fc], a0, b1[fc], acc[fr][fc]); // hi*lo
                    wmma::mma_sync(acc[fr][fc], a1, b0[fc], acc[fr][fc]); // lo*hi
                }
            }
        }
    }

#pragma unroll
    for (int fr = 0; fr < 4; fr++)
#pragma unroll
        for (int fc = 0; fc < 4; fc++)
            wmma::store_matrix_sync(C + (size_t)(m0 + wr * 64 + fr * 16) * HID_ + n0 + wc * 64 + fc * 16,
                                    acc[fr][fc], HID_, wmma::mem_row_major);
}

// ---------------------------------------------------------------------------
// Gating: beta[b][h][t] = clip(sigmoid(x_row . Wg[:,h] + bg[h]), 0.8, 0.9995)
// ---------------------------------------------------------------------------
__global__ void gate_kernel(const float* __restrict__ x,
                            const float* __restrict__ Wg,
                            const float* __restrict__ bg)
{
    int row = blockIdx.x;
    __shared__ float xs[HID_];
    __shared__ float red[256];
    for (int i = threadIdx.x; i < HID_; i += 256) xs[i] = x[(size_t)row * HID_ + i];
    __syncthreads();

    int h = threadIdx.x & 15;
    int kl = threadIdx.x >> 4;
    float acc = 0.f;
    for (int k = kl; k < HID_; k += 16) acc += xs[k] * Wg[(size_t)k * H_ + h];
    red[threadIdx.x] = acc;
    __syncthreads();
    if (threadIdx.x < 16) {
        float s = 0.f;
#pragma unroll
        for (int j = 0; j < 16; j++) s += red[threadIdx.x + 16 * j];
        float u = s + bg[threadIdx.x];
        float bv = 1.f / (1.f + expf(-u));
        bv = fminf(fmaxf(bv, 0.8f), 0.9995f);
        int b = row / L_, t = row % L_;
        g_beta[((size_t)(b * H_ + threadIdx.x)) * L_ + t] = bv;
    }
}

// ---------------------------------------------------------------------------
// RoPE + phi for q,k; relayout v.
// ---------------------------------------------------------------------------
__global__ void postproc_kernel()
{
    int bid = blockIdx.x;
    int h  = bid % H_;
    int bt = bid / H_;
    int t  = bt % L_;
    int b  = bt / L_;
    int i  = threadIdx.x;            // 0..63
    size_t in = (size_t)bt * HID_ + h * D_;
    size_t o  = ((size_t)(b * H_ + h) * L_ + t) * D_;

    float c = g_cos[t * 64 + i], s = g_sin[t * 64 + i];

    float qe = g_q[in + i], qo = g_q[in + 64 + i];
    float ke = g_k[in + i], ko = g_k[in + 64 + i];
    float r;
    r = qe * c - qo * s;  g_pq[o + i]      = (r > 0.f) ? r + 1.f : expf(r);
    r = qe * s + qo * c;  g_pq[o + 64 + i] = (r > 0.f) ? r + 1.f : expf(r);
    r = ke * c - ko * s;  g_pk[o + i]      = (r > 0.f) ? r + 1.f : expf(r);
    r = ke * s + ko * c;  g_pk[o + 64 + i] = (r > 0.f) ? r + 1.f : expf(r);

    g_vt[o + i]      = g_v[in + i];
    g_vt[o + 64 + i] = g_v[in + 64 + i];
}

// ---------------------------------------------------------------------------
// Denominator scan: z = z*b + k ; den = q.z + eps.
// One warp per (b,h); per-lane partials staged to smem, one reduce per 32 t.
// ---------------------------------------------------------------------------
__global__ void __launch_bounds__(32) denom_kernel()
{
    int bh = blockIdx.x;
    int lane = threadIdx.x;
    __shared__ float ps[32][33];
    const float4* q4 = reinterpret_cast<const float4*>(g_pq) + (size_t)bh * L_ * 32;
    const float4* k4 = reinterpret_cast<const float4*>(g_pk) + (size_t)bh * L_ * 32;
    const float* bptr = g_beta + (size_t)bh * L_;
    float* dptr = g_den + (size_t)bh * L_;
    float zx = 0.f, zy = 0.f, zz = 0.f, zw = 0.f;
    for (int t0 = 0; t0 < L_; t0 += 32) {
#pragma unroll 8
        for (int i = 0; i < 32; i++) {
            int t = t0 + i;
            float bb = bptr[t];
            float4 kk = k4[(size_t)t * 32 + lane];
            float4 qq = q4[(size_t)t * 32 + lane];
            zx = zx * bb + kk.x; zy = zy * bb + kk.y;
            zz = zz * bb + kk.z; zw = zw * bb + kk.w;
            ps[i][lane] = qq.x * zx + qq.y * zy + qq.z * zz + qq.w * zw;
        }
        __syncwarp();
        float acc = 0.f;
#pragma unroll
        for (int j = 0; j < 32; j++) acc += ps[lane][j];
        dptr[t0 + lane] = acc + 1e-6f;
        __syncwarp();
    }
}

// ---------------------------------------------------------------------------
// Main state scan. 4 e-blocks of 32 cols per (b,h). Thread (le, hf):
// le = tid>>2 (e col), hf = tid&3 (d quarter) -> partner lanes adjacent,
// reduction via 2x shfl.xor (no per-step barriers).
// ---------------------------------------------------------------------------
__global__ void __launch_bounds__(128) scan_kernel()
{
    constexpr int NT = 16;
    int bid = blockIdx.x;            // 128 blocks
    int bh = bid >> 2;
    int ec = bid & 3;
    int b = bh / H_;
    int h = bh % H_;
    int tid = threadIdx.x;
    int le = tid >> 2;               // 0..31 e column within block
    int hf = tid & 3;                // 0..3 d-quarter
    int d0 = hf * 32;

    __shared__ float qs[NT][D_], ks[NT][D_], vs[NT][32], bs[NT], ds[NT];

    const float4* pq4 = reinterpret_cast<const float4*>(g_pq) + (size_t)bh * L_ * 32;
    const float4* pk4 = reinterpret_cast<const float4*>(g_pk) + (size_t)bh * L_ * 32;
    const float4* vt4 = reinterpret_cast<const float4*>(g_vt) + (size_t)bh * L_ * 32;
    const float* bptr = g_beta + (size_t)bh * L_;
    const float* dptr = g_den  + (size_t)bh * L_;
    float* ybase = g_y + (size_t)b * L_ * HID_ + h * D_ + ec * 32;

    float S[32];
#pragma unroll
    for (int j = 0; j < 32; j++) S[j] = 0.f;

    for (int t0 = 0; t0 < L_; t0 += NT) {
#pragma unroll
        for (int id = tid; id < NT * 32; id += 128) {
            int s = id >> 5, c = id & 31;
            reinterpret_cast<float4*>(qs[s])[c] = pq4[(size_t)(t0 + s) * 32 + c];
            reinterpret_cast<float4*>(ks[s])[c] = pk4[(size_t)(t0 + s) * 32 + c];
        }
        {
            int s = tid >> 3, c = tid & 7;   // NT*8 == 128
            reinterpret_cast<float4*>(vs[s])[c] = vt4[(size_t)(t0 + s) * 32 + ec * 8 + c];
        }
        if (tid < NT) bs[tid] = bptr[t0 + tid];
        else if (tid < 2 * NT) ds[tid - NT] = dptr[t0 + tid - NT];
        __syncthreads();

#pragma unroll 1
        for (int s = 0; s < NT; ++s) {
            float bb = bs[s];
            float vv = vs[s][le];
            const float4* kq = reinterpret_cast<const float4*>(&ks[s][d0]);
            const float4* qq = reinterpret_cast<const float4*>(&qs[s][d0]);
            float p0 = 0.f, p1 = 0.f, p2 = 0.f, p3 = 0.f;
#pragma unroll
            for (int j = 0; j < 8; j++) {
                float4 kf = kq[j];
                float4 qf = qq[j];
                S[4*j+0] = S[4*j+0] * bb + kf.x * vv; p0 += qf.x * S[4*j+0];
                S[4*j+1] = S[4*j+1] * bb + kf.y * vv; p1 += qf.y * S[4*j+1];
                S[4*j+2] = S[4*j+2] * bb + kf.z * vv; p2 += qf.z * S[4*j+2];
                S[4*j+3] = S[4*j+3] * bb + kf.w * vv; p3 += qf.w * S[4*j+3];
            }
            float p = (p0 + p1) + (p2 + p3);
            p += __shfl_xor_sync(0xffffffffu, p, 1);
            p += __shfl_xor_sync(0xffffffffu, p, 2);
            if (hf == 0) ybase[(size_t)(t0 + s) * HID_ + le] = p / ds[s];
        }
        __syncthreads();
    }
}

// ---------------------------------------------------------------------------
// Bias add on final output
// ---------------------------------------------------------------------------
__global__ void bias_kernel(float* __restrict__ out, const float* __restrict__ bo, int n)
{
    int i = blockIdx.x * blockDim.x + threadIdx.x;
    if (i < n) out[i] += bo[i & (HID_ - 1)];
}

// ---------------------------------------------------------------------------
// Launch
// ---------------------------------------------------------------------------
extern "C" void kernel_launch(void* const* d_in, const int* in_sizes, int n_in,
                              void* d_out, int out_size)
{
    const float* x  = (const float*)d_in[0];
    const float* Wq = (const float*)d_in[1];
    const float* Wk = (const float*)d_in[2];
    const float* Wv = (const float*)d_in[3];
    const float* Wg = (const float*)d_in[4];
    const float* bg = (const float*)d_in[5];
    const float* Wo = (const float*)d_in[6];
    const float* bo = (const float*)d_in[7];
    float* out = (float*)d_out;

    void* p;
    __nv_bfloat16 *xh, *xl, *wh, *wl, *yh, *yl;
    float *qf, *kf, *vf, *yf;
    cudaGetSymbolAddress(&p, g_xh); xh = (__nv_bfloat16*)p;
    cudaGetSymbolAddress(&p, g_xl); xl = (__nv_bfloat16*)p;
    cudaGetSymbolAddress(&p, g_wh); wh = (__nv_bfloat16*)p;
    cudaGetSymbolAddress(&p, g_wl); wl = (__nv_bfloat16*)p;
    cudaGetSymbolAddress(&p, g_yh); yh = (__nv_bfloat16*)p;
    cudaGetSymbolAddress(&p, g_yl); yl = (__nv_bfloat16*)p;
    cudaGetSymbolAddress(&p, g_q);  qf = (float*)p;
    cudaGetSymbolAddress(&p, g_k);  kf = (float*)p;
    cudaGetSymbolAddress(&p, g_v);  vf = (float*)p;
    cudaGetSymbolAddress(&p, g_y);  yf = (float*)p;

    cudaFuncSetAttribute(gemm_split_pipe, cudaFuncAttributeMaxDynamicSharedMemorySize, GEMM_SMEM);

    const int NX = M_ * HID_;
    const size_t NW = (size_t)HID_ * HID_;
    const int TS = 256 * 8;   // elements per split block

    // 1) splits of x and all weights (vectorized, 8 elem/thread)
    split_kernel<<<(NX + TS - 1) / TS, 256>>>(x,  xh, xl, NX);
    split_kernel<<<((int)NW + TS - 1) / TS, 256>>>(Wq, wh + 0 * NW, wl + 0 * NW, (int)NW);
    split_kernel<<<((int)NW + TS - 1) / TS, 256>>>(Wk, wh + 1 * NW, wl + 1 * NW, (int)NW);
    split_kernel<<<((int)NW + TS - 1) / TS, 256>>>(Wv, wh + 2 * NW, wl + 2 * NW, (int)NW);
    split_kernel<<<((int)NW + TS - 1) / TS, 256>>>(Wo, wh + 3 * NW, wl + 3 * NW, (int)NW);
    rope_table_kernel<<<L_, 64>>>();

    // 2) projection GEMMs (pipelined, 128x256 tiles)
    dim3 gg(HID_ / BN, M_ / BM);   // (8, 32)
    gemm_split_pipe<<<gg, 256, GEMM_SMEM>>>(xh, xl, wh + 0 * NW, wl + 0 * NW, qf);
    gemm_split_pipe<<<gg, 256, GEMM_SMEM>>>(xh, xl, wh + 1 * NW, wl + 1 * NW, kf);
    gemm_split_pipe<<<gg, 256, GEMM_SMEM>>>(xh, xl, wh + 2 * NW, wl + 2 * NW, vf);

    // 3) gating + rope/phi/relayout
    gate_kernel<<<M_, 256>>>(x, Wg, bg);
    postproc_kernel<<<B_ * L_ * H_, 64>>>();

    // 4) scans
    denom_kernel<<<B_ * H_, 32>>>();
    scan_kernel<<<B_ * H_ * 4, 128>>>();

    // 5) output projection + bias
    split_kernel<<<(NX + TS - 1) / TS, 256>>>(yf, yh, yl, NX);
    gemm_split_pipe<<<gg, 256, GEMM_SMEM>>>(yh, yl, wh + 3 * NW, wl + 3 * NW, out);
    bias_kernel<<<(NX + 255) / 256, 256>>>(out, bo, NX);
}

// round 9
// speedup vs baseline: 1.6393x; 1.2312x over previous
#include <cuda_runtime.h>
#include <cuda_fp16.h>
#include <mma.h>
#include <math.h>
#include <stdint.h>

using namespace nvcuda;

// Problem constants
constexpr int B_   = 2;
constexpr int L_   = 2048;
constexpr int HID_ = 2048;
constexpr int H_   = 16;
constexpr int D_   = 128;
constexpr int M_   = B_ * L_;      // 4096 token rows
constexpr int BHL_ = B_ * H_ * L_;

// ---------------------------------------------------------------------------
// Static scratch (no cudaMalloc allowed)
// ---------------------------------------------------------------------------
__device__ __align__(16) __half g_xh[M_ * HID_];
__device__ __align__(16) __half g_xl[M_ * HID_];
__device__ __align__(16) __half g_w16[4][(size_t)HID_ * HID_];  // [K][N] fp16
__device__ __align__(16) float g_q[M_ * HID_];
__device__ __align__(16) float g_k[M_ * HID_];
__device__ __align__(16) float g_v[M_ * HID_];
__device__ __align__(16) float g_pq[M_ * HID_];   // phi(rope(q)) [b][h][t][d]
__device__ __align__(16) float g_pk[M_ * HID_];
__device__ __align__(16) float g_vt[M_ * HID_];
__device__ __align__(16) float g_beta[BHL_];
__device__ __align__(16) float g_den[BHL_];
__device__ __align__(16) float g_y[M_ * HID_];
__device__ __align__(16) __half g_yh[M_ * HID_];
__device__ __align__(16) __half g_yl[M_ * HID_];
__device__ __align__(16) float g_cos[L_ * 64];
__device__ __align__(16) float g_sin[L_ * 64];

// ---------------------------------------------------------------------------
// PTX helpers (cp.async only — tcgen05 not available: harness lowers to
// .target sm_103 without the 'a' suffix)
// ---------------------------------------------------------------------------
__device__ __forceinline__ uint32_t smem_u32(const void* p) {
    uint32_t a;
    asm("{ .reg .u64 t; cvta.to.shared.u64 t, %1; cvt.u32.u64 %0, t; }"
        : "=r"(a) : "l"(p));
    return a;
}
__device__ __forceinline__ void cp_async16(uint32_t dst, const void* src) {
    asm volatile("cp.async.cg.shared.global [%0], [%1], 16;" :: "r"(dst), "l"(src));
}
__device__ __forceinline__ void cp_commit() {
    asm volatile("cp.async.commit_group;" ::: "memory");
}
template<int N> __device__ __forceinline__ void cp_wait() {
    asm volatile("cp.async.wait_group %0;" :: "n"(N) : "memory");
}

// ---------------------------------------------------------------------------
// fp32 -> (hi, lo) fp16 split, 8 elements/thread
// ---------------------------------------------------------------------------
__global__ void split_kernel(const float* __restrict__ x,
                             __half* __restrict__ hi,
                             __half* __restrict__ lo, int n)
{
    int i = (blockIdx.x * blockDim.x + threadIdx.x) * 8;
    if (i < n) {
        float4 a = *reinterpret_cast<const float4*>(x + i);
        float4 b = *reinterpret_cast<const float4*>(x + i + 4);
        float vv[8] = {a.x, a.y, a.z, a.w, b.x, b.y, b.z, b.w};
        __half h[8], l[8];
#pragma unroll
        for (int j = 0; j < 8; j++) {
            h[j] = __float2half(vv[j]);
            l[j] = __float2half(vv[j] - __half2float(h[j]));
        }
        *reinterpret_cast<uint4*>(hi + i) = *reinterpret_cast<uint4*>(h);
        *reinterpret_cast<uint4*>(lo + i) = *reinterpret_cast<uint4*>(l);
    }
}

// ---------------------------------------------------------------------------
// fp32 -> fp16 convert (weights), 8 elements/thread
// ---------------------------------------------------------------------------
__global__ void conv16_kernel(const float* __restrict__ x,
                              __half* __restrict__ o, int n)
{
    int i = (blockIdx.x * blockDim.x + threadIdx.x) * 8;
    if (i < n) {
        float4 a = *reinterpret_cast<const float4*>(x + i);
        float4 b = *reinterpret_cast<const float4*>(x + i + 4);
        float vv[8] = {a.x, a.y, a.z, a.w, b.x, b.y, b.z, b.w};
        __half h[8];
#pragma unroll
        for (int j = 0; j < 8; j++) h[j] = __float2half(vv[j]);
        *reinterpret_cast<uint4*>(o + i) = *reinterpret_cast<uint4*>(h);
    }
}

// ---------------------------------------------------------------------------
// RoPE table
// ---------------------------------------------------------------------------
__global__ void rope_table_kernel()
{
    int t = blockIdx.x;
    int i = threadIdx.x;           // 0..63
    double inv = pow(10000.0, -(double)i / 64.0);
    float invf = (float)inv;
    float f = (float)t * invf;
    g_cos[t * 64 + i] = cosf(f);
    g_sin[t * 64 + i] = sinf(f);
}

// ---------------------------------------------------------------------------
// fp16 2-product GEMM, 4-stage cp.async pipeline.
// C = A @ B; A split (hi+lo) fp16, B single fp16.
// A [M,K] row-major, B [K,N] row-major, C [M,N] fp32.
// CTA tile 128x256, BK=32. 8 warps (2x4), warp tile 64x64 (4x4 frags).
// Error ~2^-12 (weight rounding) -> final rel_err ~2e-4, within 1e-3.
// ---------------------------------------------------------------------------
constexpr int BM = 128, BN = 256, BK = 32;
constexpr int STAGES = 4;
constexpr int LDA = 40;                  // halves: 80B row stride
constexpr int LDB = 264;                 // halves: 528B row stride
constexpr int A_SPLIT_B = BM * LDA * 2;  // 10240
constexpr int B_TILE_B  = BK * LDB * 2;  // 16896
constexpr int A_TOT_B   = 2 * A_SPLIT_B;              // 20480
constexpr int STAGE_B   = A_TOT_B + B_TILE_B;         // 37376
constexpr int GEMM_SMEM = STAGES * STAGE_B;           // 149504 (~146KB)

__device__ __forceinline__ void gemm_load_slab(
    uint32_t sbase, int stage, int tid, int m0, int n0, int k0,
    const __half* __restrict__ Ah, const __half* __restrict__ Al,
    const __half* __restrict__ Bw)
{
    uint32_t st = sbase + (uint32_t)stage * STAGE_B;
    // A: 2 splits x 128 rows x 4 chunks(16B) = 1024 chunks, 4/thread
#pragma unroll
    for (int i = 0; i < 4; i++) {
        int id = tid + i * 256;
        const __half* base = (id & 512) ? Al : Ah;
        uint32_t off = (id & 512) ? (uint32_t)A_SPLIT_B : 0u;
        int r = (id >> 2) & 127;
        int j = id & 3;
        cp_async16(st + off + r * 80 + j * 16,
                   base + (size_t)(m0 + r) * HID_ + k0 + j * 8);
    }
    // B: 32 rows x 32 chunks(16B) = 1024 chunks, 4/thread
#pragma unroll
    for (int i = 0; i < 4; i++) {
        int id = tid + i * 256;
        int r = (id >> 5) & 31;
        int j = id & 31;
        cp_async16(st + (uint32_t)A_TOT_B + r * 528 + j * 16,
                   Bw + (size_t)(k0 + r) * HID_ + n0 + j * 8);
    }
    cp_commit();
}

__global__ void __launch_bounds__(256, 1)
gemm_split_pipe(const __half* __restrict__ Ah, const __half* __restrict__ Al,
                const __half* __restrict__ Bw, float* __restrict__ C)
{
    extern __shared__ __align__(16) char smem[];

    const int tid = threadIdx.x;
    const int wid = tid >> 5;
    const int wr  = wid >> 2;   // 0..1  (64-row strip)
    const int wc  = wid & 3;    // 0..3  (64-col strip)
    const int m0  = blockIdx.y * BM;
    const int n0  = blockIdx.x * BN;

    uint32_t sbase = smem_u32(smem);

    wmma::fragment<wmma::accumulator, 16, 16, 16, float> acc[4][4];
#pragma unroll
    for (int i = 0; i < 4; i++)
#pragma unroll
        for (int j = 0; j < 4; j++) wmma::fill_fragment(acc[i][j], 0.0f);

    constexpr int NI = HID_ / BK;   // 64

    // prologue: fill STAGES-1 slabs
#pragma unroll
    for (int s = 0; s < STAGES - 1; s++)
        gemm_load_slab(sbase, s, tid, m0, n0, s * BK, Ah, Al, Bw);

#pragma unroll 1
    for (int i = 0; i < NI; i++) {
        if (i + STAGES - 1 < NI) cp_wait<STAGES - 2>();
        else                     cp_wait<0>();
        __syncthreads();   // slab i visible; all threads done with slab i-1

        if (i + STAGES - 1 < NI)
            gemm_load_slab(sbase, (i + STAGES - 1) % STAGES, tid, m0, n0,
                           (i + STAGES - 1) * BK, Ah, Al, Bw);

        const char* st = smem + (size_t)(i % STAGES) * STAGE_B;
        const __half* As0 = (const __half*)(st);
        const __half* As1 = (const __half*)(st + A_SPLIT_B);
        const __half* Bs  = (const __half*)(st + A_TOT_B);

#pragma unroll
        for (int kk = 0; kk < BK; kk += 16) {
            wmma::fragment<wmma::matrix_b, 16, 16, 16, __half, wmma::row_major> b[4];
#pragma unroll
            for (int fc = 0; fc < 4; fc++)
                wmma::load_matrix_sync(b[fc], Bs + kk * LDB + wc * 64 + fc * 16, LDB);
#pragma unroll
            for (int fr = 0; fr < 4; fr++) {
                wmma::fragment<wmma::matrix_a, 16, 16, 16, __half, wmma::row_major> a0, a1;
                wmma::load_matrix_sync(a0, As0 + (wr * 64 + fr * 16) * LDA + kk, LDA);
                wmma::load_matrix_sync(a1, As1 + (wr * 64 + fr * 16) * LDA + kk, LDA);
#pragma unroll
                for (int fc = 0; fc < 4; fc++) {
                    wmma::mma_sync(acc[fr][fc], a0, b[fc], acc[fr][fc]); // hi*B
                    wmma::mma_sync(acc[fr][fc], a1, b[fc], acc[fr][fc]); // lo*B
                }
            }
        }
    }

#pragma unroll
    for (int fr = 0; fr < 4; fr++)
#pragma unroll
        for (int fc = 0; fc < 4; fc++)
            wmma::store_matrix_sync(C + (size_t)(m0 + wr * 64 + fr * 16) * HID_ + n0 + wc * 64 + fc * 16,
                                    acc[fr][fc], HID_, wmma::mem_row_major);
}

// ---------------------------------------------------------------------------
// Gating GEMV: beta = clip(sigmoid(x @ Wg + bg), 0.8, 0.9995)
// 128 blocks x 32 rows, K chunked through smem (Wg read 128x not 4096x).
// ---------------------------------------------------------------------------
__global__ void __launch_bounds__(256) gate_kernel(const float* __restrict__ x,
                            const float* __restrict__ Wg,
                            const float* __restrict__ bg)
{
    constexpr int RB = 32;     // rows per block
    constexpr int KC = 256;    // K chunk
    __shared__ float xs[RB][KC + 1];
    __shared__ float wgs[KC * H_];

    int row0 = blockIdx.x * RB;
    int tid = threadIdx.x;
    int h  = tid & 15;
    int rg = tid >> 4;         // 0..15 -> rows rg, rg+16

    float acc0 = 0.f, acc1 = 0.f;

    for (int kc = 0; kc < HID_; kc += KC) {
        __syncthreads();
        // load Wg chunk: KC*16 = 4096 floats
#pragma unroll
        for (int i = 0; i < (KC * H_) / 256; i++)
            wgs[i * 256 + tid] = Wg[(size_t)kc * H_ + i * 256 + tid];
        // load x chunk: 32 rows x KC = 8192 floats
#pragma unroll
        for (int i = 0; i < (RB * KC) / 256; i++) {
            int idx = i * 256 + tid;
            int r = idx >> 8, c = idx & (KC - 1);
            xs[r][c] = x[(size_t)(row0 + r) * HID_ + kc + c];
        }
        __syncthreads();
#pragma unroll 4
        for (int k = 0; k < KC; k++) {
            float w = wgs[k * H_ + h];
            acc0 += xs[rg][k] * w;
            acc1 += xs[rg + 16][k] * w;
        }
    }

    float bgh = bg[h];
    {
        float u = acc0 + bgh;
        float bv = fminf(fmaxf(1.f / (1.f + expf(-u)), 0.8f), 0.9995f);
        int row = row0 + rg;
        int b = row / L_, t = row % L_;
        g_beta[((size_t)(b * H_ + h)) * L_ + t] = bv;
    }
    {
        float u = acc1 + bgh;
        float bv = fminf(fmaxf(1.f / (1.f + expf(-u)), 0.8f), 0.9995f);
        int row = row0 + rg + 16;
        int b = row / L_, t = row % L_;
        g_beta[((size_t)(b * H_ + h)) * L_ + t] = bv;
    }
}

// ---------------------------------------------------------------------------
// RoPE + phi for q,k; relayout v.
// ---------------------------------------------------------------------------
__global__ void postproc_kernel()
{
    int bid = blockIdx.x;
    int h  = bid % H_;
    int bt = bid / H_;
    int t  = bt % L_;
    int b  = bt / L_;
    int i  = threadIdx.x;            // 0..63
    size_t in = (size_t)bt * HID_ + h * D_;
    size_t o  = ((size_t)(b * H_ + h) * L_ + t) * D_;

    float c = g_cos[t * 64 + i], s = g_sin[t * 64 + i];

    float qe = g_q[in + i], qo = g_q[in + 64 + i];
    float ke = g_k[in + i], ko = g_k[in + 64 + i];
    float r;
    r = qe * c - qo * s;  g_pq[o + i]      = (r > 0.f) ? r + 1.f : expf(r);
    r = qe * s + qo * c;  g_pq[o + 64 + i] = (r > 0.f) ? r + 1.f : expf(r);
    r = ke * c - ko * s;  g_pk[o + i]      = (r > 0.f) ? r + 1.f : expf(r);
    r = ke * s + ko * c;  g_pk[o + 64 + i] = (r > 0.f) ? r + 1.f : expf(r);

    g_vt[o + i]      = g_v[in + i];
    g_vt[o + 64 + i] = g_v[in + 64 + i];
}

// ---------------------------------------------------------------------------
// Denominator scan: z = z*b + k ; den = q.z + eps.
// ---------------------------------------------------------------------------
__global__ void __launch_bounds__(32) denom_kernel()
{
    int bh = blockIdx.x;
    int lane = threadIdx.x;
    __shared__ float ps[32][33];
    const float4* q4 = reinterpret_cast<const float4*>(g_pq) + (size_t)bh * L_ * 32;
    const float4* k4 = reinterpret_cast<const float4*>(g_pk) + (size_t)bh * L_ * 32;
    const float* bptr = g_beta + (size_t)bh * L_;
    float* dptr = g_den + (size_t)bh * L_;
    float zx = 0.f, zy = 0.f, zz = 0.f, zw = 0.f;
    for (int t0 = 0; t0 < L_; t0 += 32) {
#pragma unroll 8
        for (int i = 0; i < 32; i++) {
            int t = t0 + i;
            float bb = bptr[t];
            float4 kk = k4[(size_t)t * 32 + lane];
            float4 qq = q4[(size_t)t * 32 + lane];
            zx = zx * bb + kk.x; zy = zy * bb + kk.y;
            zz = zz * bb + kk.z; zw = zw * bb + kk.w;
            ps[i][lane] = qq.x * zx + qq.y * zy + qq.z * zz + qq.w * zw;
        }
        __syncwarp();
        float acc = 0.f;
#pragma unroll
        for (int j = 0; j < 32; j++) acc += ps[lane][j];
        dptr[t0 + lane] = acc + 1e-6f;
        __syncwarp();
    }
}

// ---------------------------------------------------------------------------
// Main state scan. 4 e-blocks of 32 cols per (b,h). le = tid>>2, hf = tid&3,
// reduction via 2x shfl.xor.
// ---------------------------------------------------------------------------
__global__ void __launch_bounds__(128) scan_kernel()
{
    constexpr int NT = 16;
    int bid = blockIdx.x;            // 128 blocks
    int bh = bid >> 2;
    int ec = bid & 3;
    int b = bh / H_;
    int h = bh % H_;
    int tid = threadIdx.x;
    int le = tid >> 2;               // 0..31 e column within block
    int hf = tid & 3;                // 0..3 d-quarter
    int d0 = hf * 32;

    __shared__ float qs[NT][D_], ks[NT][D_], vs[NT][32], bs[NT], ds[NT];

    const float4* pq4 = reinterpret_cast<const float4*>(g_pq) + (size_t)bh * L_ * 32;
    const float4* pk4 = reinterpret_cast<const float4*>(g_pk) + (size_t)bh * L_ * 32;
    const float4* vt4 = reinterpret_cast<const float4*>(g_vt) + (size_t)bh * L_ * 32;
    const float* bptr = g_beta + (size_t)bh * L_;
    const float* dptr = g_den  + (size_t)bh * L_;
    float* ybase = g_y + (size_t)b * L_ * HID_ + h * D_ + ec * 32;

    float S[32];
#pragma unroll
    for (int j = 0; j < 32; j++) S[j] = 0.f;

    for (int t0 = 0; t0 < L_; t0 += NT) {
#pragma unroll
        for (int id = tid; id < NT * 32; id += 128) {
            int s = id >> 5, c = id & 31;
            reinterpret_cast<float4*>(qs[s])[c] = pq4[(size_t)(t0 + s) * 32 + c];
            reinterpret_cast<float4*>(ks[s])[c] = pk4[(size_t)(t0 + s) * 32 + c];
        }
        {
            int s = tid >> 3, c = tid & 7;   // NT*8 == 128
            reinterpret_cast<float4*>(vs[s])[c] = vt4[(size_t)(t0 + s) * 32 + ec * 8 + c];
        }
        if (tid < NT) bs[tid] = bptr[t0 + tid];
        else if (tid < 2 * NT) ds[tid - NT] = dptr[t0 + tid - NT];
        __syncthreads();

#pragma unroll 1
        for (int s = 0; s < NT; ++s) {
            float bb = bs[s];
            float vv = vs[s][le];
            const float4* kq = reinterpret_cast<const float4*>(&ks[s][d0]);
            const float4* qq = reinterpret_cast<const float4*>(&qs[s][d0]);
            float p0 = 0.f, p1 = 0.f, p2 = 0.f, p3 = 0.f;
#pragma unroll
            for (int j = 0; j < 8; j++) {
                float4 kf = kq[j];
                float4 qf = qq[j];
                S[4*j+0] = S[4*j+0] * bb + kf.x * vv; p0 += qf.x * S[4*j+0];
                S[4*j+1] = S[4*j+1] * bb + kf.y * vv; p1 += qf.y * S[4*j+1];
                S[4*j+2] = S[4*j+2] * bb + kf.z * vv; p2 += qf.z * S[4*j+2];
                S[4*j+3] = S[4*j+3] * bb + kf.w * vv; p3 += qf.w * S[4*j+3];
            }
            float p = (p0 + p1) + (p2 + p3);
            p += __shfl_xor_sync(0xffffffffu, p, 1);
            p += __shfl_xor_sync(0xffffffffu, p, 2);
            if (hf == 0) ybase[(size_t)(t0 + s) * HID_ + le] = p / ds[s];
        }
        __syncthreads();
    }
}

// ---------------------------------------------------------------------------
// Bias add on final output
// ---------------------------------------------------------------------------
__global__ void bias_kernel(float* __restrict__ out, const float* __restrict__ bo, int n)
{
    int i = blockIdx.x * blockDim.x + threadIdx.x;
    if (i < n) out[i] += bo[i & (HID_ - 1)];
}

// ---------------------------------------------------------------------------
// Launch
// ---------------------------------------------------------------------------
extern "C" void kernel_launch(void* const* d_in, const int* in_sizes, int n_in,
                              void* d_out, int out_size)
{
    const float* x  = (const float*)d_in[0];
    const float* Wq = (const float*)d_in[1];
    const float* Wk = (const float*)d_in[2];
    const float* Wv = (const float*)d_in[3];
    const float* Wg = (const float*)d_in[4];
    const float* bg = (const float*)d_in[5];
    const float* Wo = (const float*)d_in[6];
    const float* bo = (const float*)d_in[7];
    float* out = (float*)d_out;

    void* p;
    __half *xh, *xl, *w16, *yh, *yl;
    float *qf, *kf, *vf, *yf;
    cudaGetSymbolAddress(&p, g_xh);  xh  = (__half*)p;
    cudaGetSymbolAddress(&p, g_xl);  xl  = (__half*)p;
    cudaGetSymbolAddress(&p, g_w16); w16 = (__half*)p;
    cudaGetSymbolAddress(&p, g_yh);  yh  = (__half*)p;
    cudaGetSymbolAddress(&p, g_yl);  yl  = (__half*)p;
    cudaGetSymbolAddress(&p, g_q);   qf  = (float*)p;
    cudaGetSymbolAddress(&p, g_k);   kf  = (float*)p;
    cudaGetSymbolAddress(&p, g_v);   vf  = (float*)p;
    cudaGetSymbolAddress(&p, g_y);   yf  = (float*)p;

    cudaFuncSetAttribute(gemm_split_pipe, cudaFuncAttributeMaxDynamicSharedMemorySize, GEMM_SMEM);

    const int NX = M_ * HID_;
    const size_t NW = (size_t)HID_ * HID_;
    const int TS = 256 * 8;   // elements per split/conv block

    // 1) split x (fp16 hi/lo); convert weights to fp16
    split_kernel<<<(NX + TS - 1) / TS, 256>>>(x, xh, xl, NX);
    conv16_kernel<<<((int)NW + TS - 1) / TS, 256>>>(Wq, w16 + 0 * NW, (int)NW);
    conv16_kernel<<<((int)NW + TS - 1) / TS, 256>>>(Wk, w16 + 1 * NW, (int)NW);
    conv16_kernel<<<((int)NW + TS - 1) / TS, 256>>>(Wv, w16 + 2 * NW, (int)NW);
    conv16_kernel<<<((int)NW + TS - 1) / TS, 256>>>(Wo, w16 + 3 * NW, (int)NW);
    rope_table_kernel<<<L_, 64>>>();

    // 2) projection GEMMs
    dim3 gg(HID_ / BN, M_ / BM);   // (8, 32)
    gemm_split_pipe<<<gg, 256, GEMM_SMEM>>>(xh, xl, w16 + 0 * NW, qf);
    gemm_split_pipe<<<gg, 256, GEMM_SMEM>>>(xh, xl, w16 + 1 * NW, kf);
    gemm_split_pipe<<<gg, 256, GEMM_SMEM>>>(xh, xl, w16 + 2 * NW, vf);

    // 3) gating + rope/phi/relayout
    gate_kernel<<<M_ / 32, 256>>>(x, Wg, bg);
    postproc_kernel<<<B_ * L_ * H_, 64>>>();

    // 4) scans
    denom_kernel<<<B_ * H_, 32>>>();
    scan_kernel<<<B_ * H_ * 4, 128>>>();

    // 5) output projection + bias
    split_kernel<<<(NX + TS - 1) / TS, 256>>>(yf, yh, yl, NX);
    gemm_split_pipe<<<gg, 256, GEMM_SMEM>>>(yh, yl, w16 + 3 * NW, out);
    bias_kernel<<<(NX + 255) / 256, 256>>>(out, bo, NX);
}

// round 10
// speedup vs baseline: 1.8618x; 1.1357x over previous
#include <cuda_runtime.h>
#include <cuda_fp16.h>
#include <mma.h>
#include <math.h>
#include <stdint.h>

using namespace nvcuda;

// Problem constants
constexpr int B_   = 2;
constexpr int L_   = 2048;
constexpr int HID_ = 2048;
constexpr int H_   = 16;
constexpr int D_   = 128;
constexpr int M_   = B_ * L_;      // 4096 token rows
constexpr int BHL_ = B_ * H_ * L_;
constexpr int NQKV = 3 * HID_;     // 6144

// ---------------------------------------------------------------------------
// Static scratch (no cudaMalloc allowed)
// ---------------------------------------------------------------------------
__device__ __align__(16) __half g_xh[M_ * HID_];                 // fp16 activations
__device__ __align__(16) __half g_wqkv[(size_t)HID_ * NQKV];    // [K][3N] fp16
__device__ __align__(16) __half g_wo[(size_t)HID_ * HID_];      // [K][N] fp16
__device__ __align__(16) float g_qkv[(size_t)M_ * NQKV];        // q|k|v fused output
__device__ __align__(16) float g_pq[M_ * HID_];   // phi(rope(q)) [b][h][t][d]
__device__ __align__(16) float g_pk[M_ * HID_];
__device__ __align__(16) float g_vt[M_ * HID_];
__device__ __align__(16) float g_beta[BHL_];
__device__ __align__(16) float g_den[BHL_];
__device__ __align__(16) float g_y[M_ * HID_];
__device__ __align__(16) __half g_yh[M_ * HID_];
__device__ __align__(16) float g_cos[L_ * 64];
__device__ __align__(16) float g_sin[L_ * 64];

// ---------------------------------------------------------------------------
// PTX helpers (cp.async only — tcgen05 not available: harness lowers to
// .target sm_103 without the 'a' suffix)
// ---------------------------------------------------------------------------
__device__ __forceinline__ uint32_t smem_u32(const void* p) {
    uint32_t a;
    asm("{ .reg .u64 t; cvta.to.shared.u64 t, %1; cvt.u32.u64 %0, t; }"
        : "=r"(a) : "l"(p));
    return a;
}
__device__ __forceinline__ void cp_async16(uint32_t dst, const void* src) {
    asm volatile("cp.async.cg.shared.global [%0], [%1], 16;" :: "r"(dst), "l"(src));
}
__device__ __forceinline__ void cp_commit() {
    asm volatile("cp.async.commit_group;" ::: "memory");
}
template<int N> __device__ __forceinline__ void cp_wait() {
    asm volatile("cp.async.wait_group %0;" :: "n"(N) : "memory");
}

// ---------------------------------------------------------------------------
// fp32 -> fp16 convert, 8 elements/thread
// ---------------------------------------------------------------------------
__global__ void conv16_kernel(const float* __restrict__ x,
                              __half* __restrict__ o, int n)
{
    int i = (blockIdx.x * blockDim.x + threadIdx.x) * 8;
    if (i < n) {
        float4 a = *reinterpret_cast<const float4*>(x + i);
        float4 b = *reinterpret_cast<const float4*>(x + i + 4);
        float vv[8] = {a.x, a.y, a.z, a.w, b.x, b.y, b.z, b.w};
        __half h[8];
#pragma unroll
        for (int j = 0; j < 8; j++) h[j] = __float2half(vv[j]);
        *reinterpret_cast<uint4*>(o + i) = *reinterpret_cast<uint4*>(h);
    }
}

// ---------------------------------------------------------------------------
// Weight convert into concatenated layout: dst[k*stride + base + n] = W[k][n]
// ---------------------------------------------------------------------------
__global__ void convw_kernel(const float* __restrict__ W,
                             __half* __restrict__ dst, int stride, int base)
{
    int i = (blockIdx.x * blockDim.x + threadIdx.x) * 8;   // over 2048*2048
    int k = i >> 11;            // /2048
    int n = i & (HID_ - 1);
    float4 a = *reinterpret_cast<const float4*>(W + i);
    float4 b = *reinterpret_cast<const float4*>(W + i + 4);
    float vv[8] = {a.x, a.y, a.z, a.w, b.x, b.y, b.z, b.w};
    __half h[8];
#pragma unroll
    for (int j = 0; j < 8; j++) h[j] = __float2half(vv[j]);
    *reinterpret_cast<uint4*>(dst + (size_t)k * stride + base + n) =
        *reinterpret_cast<uint4*>(h);
}

// ---------------------------------------------------------------------------
// RoPE table
// ---------------------------------------------------------------------------
__global__ void rope_table_kernel()
{
    int t = blockIdx.x;
    int i = threadIdx.x;           // 0..63
    double inv = pow(10000.0, -(double)i / 64.0);
    float invf = (float)inv;
    float f = (float)t * invf;
    g_cos[t * 64 + i] = cosf(f);
    g_sin[t * 64 + i] = sinf(f);
}

// ---------------------------------------------------------------------------
// Pure-fp16 GEMM, 5-stage cp.async pipeline.
// C = A @ B; A [M,K] fp16 row-major, B [K,N] fp16 row-major, C [M,N] fp32.
// CTA tile 128x256, BK=32. 8 warps (2x4), warp tile 64x64 (4x4 frags).
// N (= B/C row stride) is a runtime parameter (6144 for fused QKV, 2048 out).
// ---------------------------------------------------------------------------
constexpr int BM = 128, BN = 256, BK = 32;
constexpr int STAGES = 5;
constexpr int LDA = 40;                  // halves: 80B row stride
constexpr int LDB = 264;                 // halves: 528B row stride
constexpr int A_TILE_B = BM * LDA * 2;   // 10240
constexpr int B_TILE_B = BK * LDB * 2;   // 16896
constexpr int STAGE_B  = A_TILE_B + B_TILE_B;       // 27136
constexpr int GEMM_SMEM = STAGES * STAGE_B;         // 135680 (~132.5KB)

__device__ __forceinline__ void gemm_load_slab(
    uint32_t sbase, int stage, int tid, int m0, int n0, int k0, int Ndim,
    const __half* __restrict__ A, const __half* __restrict__ Bw)
{
    uint32_t st = sbase + (uint32_t)stage * STAGE_B;
    // A: 128 rows x 4 chunks(16B) = 512 chunks, 2/thread
#pragma unroll
    for (int i = 0; i < 2; i++) {
        int id = tid + i * 256;
        int r = (id >> 2) & 127;
        int j = id & 3;
        cp_async16(st + r * 80 + j * 16,
                   A + (size_t)(m0 + r) * HID_ + k0 + j * 8);
    }
    // B: 32 rows x 32 chunks(16B) = 1024 chunks, 4/thread
#pragma unroll
    for (int i = 0; i < 4; i++) {
        int id = tid + i * 256;
        int r = (id >> 5) & 31;
        int j = id & 31;
        cp_async16(st + (uint32_t)A_TILE_B + r * 528 + j * 16,
                   Bw + (size_t)(k0 + r) * Ndim + n0 + j * 8);
    }
    cp_commit();
}

__global__ void __launch_bounds__(256, 1)
gemm_fp16_pipe(const __half* __restrict__ A, const __half* __restrict__ Bw,
               float* __restrict__ C, int Ndim)
{
    extern __shared__ __align__(16) char smem[];

    const int tid = threadIdx.x;
    const int wid = tid >> 5;
    const int wr  = wid >> 2;   // 0..1  (64-row strip)
    const int wc  = wid & 3;    // 0..3  (64-col strip)
    const int m0  = blockIdx.y * BM;
    const int n0  = blockIdx.x * BN;

    uint32_t sbase = smem_u32(smem);

    wmma::fragment<wmma::accumulator, 16, 16, 16, float> acc[4][4];
#pragma unroll
    for (int i = 0; i < 4; i++)
#pragma unroll
        for (int j = 0; j < 4; j++) wmma::fill_fragment(acc[i][j], 0.0f);

    constexpr int NI = HID_ / BK;   // 64

    // prologue: fill STAGES-1 slabs
#pragma unroll
    for (int s = 0; s < STAGES - 1; s++)
        gemm_load_slab(sbase, s, tid, m0, n0, s * BK, Ndim, A, Bw);

#pragma unroll 1
    for (int i = 0; i < NI; i++) {
        if (i + STAGES - 1 < NI) cp_wait<STAGES - 2>();
        else                     cp_wait<0>();
        __syncthreads();   // slab i visible; all threads done with slab i-1

        if (i + STAGES - 1 < NI)
            gemm_load_slab(sbase, (i + STAGES - 1) % STAGES, tid, m0, n0,
                           (i + STAGES - 1) * BK, Ndim, A, Bw);

        const char* st = smem + (size_t)(i % STAGES) * STAGE_B;
        const __half* As = (const __half*)(st);
        const __half* Bs = (const __half*)(st + A_TILE_B);

#pragma unroll
        for (int kk = 0; kk < BK; kk += 16) {
            wmma::fragment<wmma::matrix_b, 16, 16, 16, __half, wmma::row_major> b[4];
#pragma unroll
            for (int fc = 0; fc < 4; fc++)
                wmma::load_matrix_sync(b[fc], Bs + kk * LDB + wc * 64 + fc * 16, LDB);
#pragma unroll
            for (int fr = 0; fr < 4; fr++) {
                wmma::fragment<wmma::matrix_a, 16, 16, 16, __half, wmma::row_major> a0;
                wmma::load_matrix_sync(a0, As + (wr * 64 + fr * 16) * LDA + kk, LDA);
#pragma unroll
                for (int fc = 0; fc < 4; fc++)
                    wmma::mma_sync(acc[fr][fc], a0, b[fc], acc[fr][fc]);
            }
        }
    }

#pragma unroll
    for (int fr = 0; fr < 4; fr++)
#pragma unroll
        for (int fc = 0; fc < 4; fc++)
            wmma::store_matrix_sync(C + (size_t)(m0 + wr * 64 + fr * 16) * Ndim + n0 + wc * 64 + fc * 16,
                                    acc[fr][fc], Ndim, wmma::mem_row_major);
}

// ---------------------------------------------------------------------------
// Gating GEMV: beta = clip(sigmoid(x @ Wg + bg), 0.8, 0.9995)
// 128 blocks x 32 rows, K chunked through smem.
// ---------------------------------------------------------------------------
__global__ void __launch_bounds__(256) gate_kernel(const float* __restrict__ x,
                            const float* __restrict__ Wg,
                            const float* __restrict__ bg)
{
    constexpr int RB = 32;     // rows per block
    constexpr int KC = 256;    // K chunk
    __shared__ float xs[RB][KC + 1];
    __shared__ float wgs[KC * H_];

    int row0 = blockIdx.x * RB;
    int tid = threadIdx.x;
    int h  = tid & 15;
    int rg = tid >> 4;         // 0..15 -> rows rg, rg+16

    float acc0 = 0.f, acc1 = 0.f;

    for (int kc = 0; kc < HID_; kc += KC) {
        __syncthreads();
#pragma unroll
        for (int i = 0; i < (KC * H_) / 256; i++)
            wgs[i * 256 + tid] = Wg[(size_t)kc * H_ + i * 256 + tid];
#pragma unroll
        for (int i = 0; i < (RB * KC) / 256; i++) {
            int idx = i * 256 + tid;
            int r = idx >> 8, c = idx & (KC - 1);
            xs[r][c] = x[(size_t)(row0 + r) * HID_ + kc + c];
        }
        __syncthreads();
#pragma unroll 4
        for (int k = 0; k < KC; k++) {
            float w = wgs[k * H_ + h];
            acc0 += xs[rg][k] * w;
            acc1 += xs[rg + 16][k] * w;
        }
    }

    float bgh = bg[h];
    {
        float u = acc0 + bgh;
        float bv = fminf(fmaxf(1.f / (1.f + expf(-u)), 0.8f), 0.9995f);
        int row = row0 + rg;
        int b = row / L_, t = row % L_;
        g_beta[((size_t)(b * H_ + h)) * L_ + t] = bv;
    }
    {
        float u = acc1 + bgh;
        float bv = fminf(fmaxf(1.f / (1.f + expf(-u)), 0.8f), 0.9995f);
        int row = row0 + rg + 16;
        int b = row / L_, t = row % L_;
        g_beta[((size_t)(b * H_ + h)) * L_ + t] = bv;
    }
}

// ---------------------------------------------------------------------------
// RoPE + phi for q,k; relayout v. Reads from fused qkv buffer.
// ---------------------------------------------------------------------------
__global__ void postproc_kernel()
{
    int bid = blockIdx.x;
    int h  = bid % H_;
    int bt = bid / H_;
    int t  = bt % L_;
    int b  = bt / L_;
    int i  = threadIdx.x;            // 0..63
    size_t in = (size_t)bt * NQKV + h * D_;
    size_t o  = ((size_t)(b * H_ + h) * L_ + t) * D_;

    float c = g_cos[t * 64 + i], s = g_sin[t * 64 + i];

    float qe = g_qkv[in + i],            qo = g_qkv[in + 64 + i];
    float ke = g_qkv[in + HID_ + i],     ko = g_qkv[in + HID_ + 64 + i];
    float r;
    r = qe * c - qo * s;  g_pq[o + i]      = (r > 0.f) ? r + 1.f : expf(r);
    r = qe * s + qo * c;  g_pq[o + 64 + i] = (r > 0.f) ? r + 1.f : expf(r);
    r = ke * c - ko * s;  g_pk[o + i]      = (r > 0.f) ? r + 1.f : expf(r);
    r = ke * s + ko * c;  g_pk[o + 64 + i] = (r > 0.f) ? r + 1.f : expf(r);

    g_vt[o + i]      = g_qkv[in + 2 * HID_ + i];
    g_vt[o + 64 + i] = g_qkv[in + 2 * HID_ + 64 + i];
}

// ---------------------------------------------------------------------------
// Denominator scan: z = z*b + k ; den = q.z + eps.
// ---------------------------------------------------------------------------
__global__ void __launch_bounds__(32) denom_kernel()
{
    int bh = blockIdx.x;
    int lane = threadIdx.x;
    __shared__ float ps[32][33];
    const float4* q4 = reinterpret_cast<const float4*>(g_pq) + (size_t)bh * L_ * 32;
    const float4* k4 = reinterpret_cast<const float4*>(g_pk) + (size_t)bh * L_ * 32;
    const float* bptr = g_beta + (size_t)bh * L_;
    float* dptr = g_den + (size_t)bh * L_;
    float zx = 0.f, zy = 0.f, zz = 0.f, zw = 0.f;
    for (int t0 = 0; t0 < L_; t0 += 32) {
#pragma unroll 8
        for (int i = 0; i < 32; i++) {
            int t = t0 + i;
            float bb = bptr[t];
            float4 kk = k4[(size_t)t * 32 + lane];
            float4 qq = q4[(size_t)t * 32 + lane];
            zx = zx * bb + kk.x; zy = zy * bb + kk.y;
            zz = zz * bb + kk.z; zw = zw * bb + kk.w;
            ps[i][lane] = qq.x * zx + qq.y * zy + qq.z * zz + qq.w * zw;
        }
        __syncwarp();
        float acc = 0.f;
#pragma unroll
        for (int j = 0; j < 32; j++) acc += ps[lane][j];
        dptr[t0 + lane] = acc + 1e-6f;
        __syncwarp();
    }
}

// ---------------------------------------------------------------------------
// Main state scan. 4 e-blocks of 32 cols per (b,h). le = tid>>2, hf = tid&3,
// reduction via 2x shfl.xor.
// ---------------------------------------------------------------------------
__global__ void __launch_bounds__(128) scan_kernel()
{
    constexpr int NT = 16;
    int bid = blockIdx.x;            // 128 blocks
    int bh = bid >> 2;
    int ec = bid & 3;
    int b = bh / H_;
    int h = bh % H_;
    int tid = threadIdx.x;
    int le = tid >> 2;               // 0..31 e column within block
    int hf = tid & 3;                // 0..3 d-quarter
    int d0 = hf * 32;

    __shared__ float qs[NT][D_], ks[NT][D_], vs[NT][32], bs[NT], ds[NT];

    const float4* pq4 = reinterpret_cast<const float4*>(g_pq) + (size_t)bh * L_ * 32;
    const float4* pk4 = reinterpret_cast<const float4*>(g_pk) + (size_t)bh * L_ * 32;
    const float4* vt4 = reinterpret_cast<const float4*>(g_vt) + (size_t)bh * L_ * 32;
    const float* bptr = g_beta + (size_t)bh * L_;
    const float* dptr = g_den  + (size_t)bh * L_;
    float* ybase = g_y + (size_t)b * L_ * HID_ + h * D_ + ec * 32;

    float S[32];
#pragma unroll
    for (int j = 0; j < 32; j++) S[j] = 0.f;

    for (int t0 = 0; t0 < L_; t0 += NT) {
#pragma unroll
        for (int id = tid; id < NT * 32; id += 128) {
            int s = id >> 5, c = id & 31;
            reinterpret_cast<float4*>(qs[s])[c] = pq4[(size_t)(t0 + s) * 32 + c];
            reinterpret_cast<float4*>(ks[s])[c] = pk4[(size_t)(t0 + s) * 32 + c];
        }
        {
            int s = tid >> 3, c = tid & 7;   // NT*8 == 128
            reinterpret_cast<float4*>(vs[s])[c] = vt4[(size_t)(t0 + s) * 32 + ec * 8 + c];
        }
        if (tid < NT) bs[tid] = bptr[t0 + tid];
        else if (tid < 2 * NT) ds[tid - NT] = dptr[t0 + tid - NT];
        __syncthreads();

#pragma unroll 1
        for (int s = 0; s < NT; ++s) {
            float bb = bs[s];
            float vv = vs[s][le];
            const float4* kq = reinterpret_cast<const float4*>(&ks[s][d0]);
            const float4* qq = reinterpret_cast<const float4*>(&qs[s][d0]);
            float p0 = 0.f, p1 = 0.f, p2 = 0.f, p3 = 0.f;
#pragma unroll
            for (int j = 0; j < 8; j++) {
                float4 kf = kq[j];
                float4 qf = qq[j];
                S[4*j+0] = S[4*j+0] * bb + kf.x * vv; p0 += qf.x * S[4*j+0];
                S[4*j+1] = S[4*j+1] * bb + kf.y * vv; p1 += qf.y * S[4*j+1];
                S[4*j+2] = S[4*j+2] * bb + kf.z * vv; p2 += qf.z * S[4*j+2];
                S[4*j+3] = S[4*j+3] * bb + kf.w * vv; p3 += qf.w * S[4*j+3];
            }
            float p = (p0 + p1) + (p2 + p3);
            p += __shfl_xor_sync(0xffffffffu, p, 1);
            p += __shfl_xor_sync(0xffffffffu, p, 2);
            if (hf == 0) ybase[(size_t)(t0 + s) * HID_ + le] = p / ds[s];
        }
        __syncthreads();
    }
}

// ---------------------------------------------------------------------------
// Bias add on final output
// ---------------------------------------------------------------------------
__global__ void bias_kernel(float* __restrict__ out, const float* __restrict__ bo, int n)
{
    int i = blockIdx.x * blockDim.x + threadIdx.x;
    if (i < n) out[i] += bo[i & (HID_ - 1)];
}

// ---------------------------------------------------------------------------
// Launch
// ---------------------------------------------------------------------------
extern "C" void kernel_launch(void* const* d_in, const int* in_sizes, int n_in,
                              void* d_out, int out_size)
{
    const float* x  = (const float*)d_in[0];
    const float* Wq = (const float*)d_in[1];
    const float* Wk = (const float*)d_in[2];
    const float* Wv = (const float*)d_in[3];
    const float* Wg = (const float*)d_in[4];
    const float* bg = (const float*)d_in[5];
    const float* Wo = (const float*)d_in[6];
    const float* bo = (const float*)d_in[7];
    float* out = (float*)d_out;

    void* p;
    __half *xh, *wqkv, *wo, *yh;
    float *qkv, *yf;
    cudaGetSymbolAddress(&p, g_xh);   xh   = (__half*)p;
    cudaGetSymbolAddress(&p, g_wqkv); wqkv = (__half*)p;
    cudaGetSymbolAddress(&p, g_wo);   wo   = (__half*)p;
    cudaGetSymbolAddress(&p, g_yh);   yh   = (__half*)p;
    cudaGetSymbolAddress(&p, g_qkv);  qkv  = (float*)p;
    cudaGetSymbolAddress(&p, g_y);    yf   = (float*)p;

    cudaFuncSetAttribute(gemm_fp16_pipe, cudaFuncAttributeMaxDynamicSharedMemorySize, GEMM_SMEM);

    const int NX = M_ * HID_;
    const size_t NW = (size_t)HID_ * HID_;
    const int TS = 256 * 8;   // elements per convert block

    // 1) converts: x -> fp16; weights -> fp16 (QKV concatenated [K][6144])
    conv16_kernel<<<(NX + TS - 1) / TS, 256>>>(x, xh, NX);
    convw_kernel<<<((int)NW + TS - 1) / TS, 256>>>(Wq, wqkv, NQKV, 0);
    convw_kernel<<<((int)NW + TS - 1) / TS, 256>>>(Wk, wqkv, NQKV, HID_);
    convw_kernel<<<((int)NW + TS - 1) / TS, 256>>>(Wv, wqkv, NQKV, 2 * HID_);
    convw_kernel<<<((int)NW + TS - 1) / TS, 256>>>(Wo, wo, HID_, 0);
    rope_table_kernel<<<L_, 64>>>();

    // 2) fused QKV projection GEMM (one launch, 768 CTAs)
    dim3 gq(NQKV / BN, M_ / BM);   // (24, 32)
    gemm_fp16_pipe<<<gq, 256, GEMM_SMEM>>>(xh, wqkv, qkv, NQKV);

    // 3) gating + rope/phi/relayout
    gate_kernel<<<M_ / 32, 256>>>(x, Wg, bg);
    postproc_kernel<<<B_ * L_ * H_, 64>>>();

    // 4) scans
    denom_kernel<<<B_ * H_, 32>>>();
    scan_kernel<<<B_ * H_ * 4, 128>>>();

    // 5) output projection + bias
    conv16_kernel<<<(NX + TS - 1) / TS, 256>>>(yf, yh, NX);
    dim3 go(HID_ / BN, M_ / BM);   // (8, 32)
    gemm_fp16_pipe<<<go, 256, GEMM_SMEM>>>(yh, wo, out, HID_);
    bias_kernel<<<(NX + 255) / 256, 256>>>(out, bo, NX);
}